// round 9
// baseline (speedup 1.0000x reference)
#include <cuda_runtime.h>
#include <math.h>
#include <stdint.h>

#define BSZ 2
#define T   2048
#define E   1024
#define H   16
#define D   64

__device__ float g_q[BSZ*T*E];
__device__ float g_k[BSZ*T*E];
__device__ float g_v[BSZ*T*E];
__device__ float g_attn[BSZ*T*E];

// ===========================================================================
// Helpers
// ===========================================================================
__device__ __forceinline__ uint32_t su32(const void* p) {
    return (uint32_t)__cvta_generic_to_shared(p);
}
__device__ __forceinline__ float tf32f(float x) {
    uint32_t u; asm("cvt.rna.tf32.f32 %0, %1;" : "=r"(u) : "f"(x));
    return __uint_as_float(u);
}
__device__ __forceinline__ uint32_t tf32u(float x) {
    uint32_t u; asm("cvt.rna.tf32.f32 %0, %1;" : "=r"(u) : "f"(x));
    return u;
}
__device__ __forceinline__ void mma8(float c[4], const uint32_t a[4],
                                     uint32_t b0, uint32_t b1) {
    asm("mma.sync.aligned.m16n8k8.row.col.f32.tf32.tf32.f32 "
        "{%0,%1,%2,%3},{%4,%5,%6,%7},{%8,%9},{%0,%1,%2,%3};"
        : "+f"(c[0]), "+f"(c[1]), "+f"(c[2]), "+f"(c[3])
        : "r"(a[0]), "r"(a[1]), "r"(a[2]), "r"(a[3]), "r"(b0), "r"(b1));
}
__device__ __forceinline__ void cp16(uint32_t dst, const void* src) {
    asm volatile("cp.async.cg.shared.global [%0], [%1], 16;"
                 :: "r"(dst), "l"(src) : "memory");
}
__device__ __forceinline__ void cp_commit() {
    asm volatile("cp.async.commit_group;" ::: "memory");
}
template <int N>
__device__ __forceinline__ void cp_wait() {
    asm volatile("cp.async.wait_group %0;" :: "n"(N) : "memory");
}

// ===========================================================================
// tf32 mma.sync GEMM core: C[M,N] = A[M,K] @ W[N,K]^T
// CTA 128x256, 512 threads (16 warps, warp 32x64), BK=32, 4-stage cp.async.
// cvt=1: round outputs to tf32 (rna) in the epilogue — lets downstream
// attention consume q/k/v without any per-fragment cvt (identical numerics).
// ===========================================================================
#define KDIM 1024
#define MT   128
#define NT   256
#define BKF  32
#define GPAD 36
#define G_AOFF 0
#define G_WOFF (MT*GPAD*4)
#define G_STAGE ((MT+NT)*GPAD*4)             // 55296 B
#define G_SMEM (4*G_STAGE)                   // 221184 B

__device__ __forceinline__ void gemm_core(const float* __restrict__ A,
                                          const float* __restrict__ W,
                                          float* __restrict__ C,
                                          int cvt, float* sg) {
    const uint32_t sbase = su32(sg);
    const int tid  = threadIdx.x;
    const int wid  = tid >> 5, lane = tid & 31;
    const int g    = lane >> 2, q = lane & 3;
    const int wr   = wid & 3;
    const int wc   = wid >> 2;
    const int bm   = blockIdx.y * MT;
    const int bn   = blockIdx.x * NT;

    const float* gA = A + (size_t)bm * KDIM;
    const float* gW = W + (size_t)bn * KDIM;

    auto cp_stage = [&](int s, int kt) {
        const uint32_t base = sbase + s * G_STAGE;
        const int k0 = kt * BKF;
        #pragma unroll
        for (int i = 0; i < 6; i++) {
            int c = tid + i * 512;
            if (c < 1024) {
                int row = c >> 3, ch = c & 7;
                cp16(base + G_AOFF + (row * GPAD + ch * 4) * 4,
                     gA + (size_t)row * KDIM + k0 + ch * 4);
            } else {
                int cc = c - 1024;
                int row = cc >> 3, ch = cc & 7;
                cp16(base + G_WOFF + (row * GPAD + ch * 4) * 4,
                     gW + (size_t)row * KDIM + k0 + ch * 4);
            }
        }
        cp_commit();
    };

    float acc[2][8][4];
    #pragma unroll
    for (int mi = 0; mi < 2; mi++)
        #pragma unroll
        for (int ni = 0; ni < 8; ni++)
            #pragma unroll
            for (int e = 0; e < 4; e++) acc[mi][ni][e] = 0.f;

    cp_stage(0, 0); cp_stage(1, 1); cp_stage(2, 2);

    const int NKT = KDIM / BKF;
    for (int kt = 0; kt < NKT; kt++) {
        cp_wait<2>();
        __syncthreads();
        if (kt + 3 < NKT) cp_stage((kt + 3) & 3, kt + 3);
        else              cp_commit();

        const float* As = sg + ((kt & 3) * G_STAGE) / 4;
        const float* Ws = As + MT * GPAD;
        const int m0 = wr * 32, n0 = wc * 64;

        #pragma unroll
        for (int kc = 0; kc < 4; kc++) {
            uint32_t af[2][4];
            #pragma unroll
            for (int mi = 0; mi < 2; mi++) {
                const float* ap = As + (m0 + mi * 16 + g) * GPAD + kc * 8 + q;
                af[mi][0] = tf32u(ap[0]);
                af[mi][1] = tf32u(ap[8 * GPAD]);
                af[mi][2] = tf32u(ap[4]);
                af[mi][3] = tf32u(ap[8 * GPAD + 4]);
            }
            #pragma unroll
            for (int ni = 0; ni < 8; ni++) {
                const float* wp = Ws + (n0 + ni * 8 + g) * GPAD + kc * 8 + q;
                uint32_t b0 = tf32u(wp[0]);
                uint32_t b1 = tf32u(wp[4]);
                mma8(acc[0][ni], af[0], b0, b1);
                mma8(acc[1][ni], af[1], b0, b1);
            }
        }
    }

    #pragma unroll
    for (int mi = 0; mi < 2; mi++) {
        const int r0 = bm + wr * 32 + mi * 16 + g;
        #pragma unroll
        for (int ni = 0; ni < 8; ni++) {
            const int col = bn + wc * 64 + ni * 8 + 2 * q;
            float o00 = acc[mi][ni][0], o01 = acc[mi][ni][1];
            float o10 = acc[mi][ni][2], o11 = acc[mi][ni][3];
            if (cvt) { o00 = tf32f(o00); o01 = tf32f(o01);
                       o10 = tf32f(o10); o11 = tf32f(o11); }
            *(float2*)(C + (size_t)r0 * E + col)       = make_float2(o00, o01);
            *(float2*)(C + (size_t)(r0 + 8) * E + col) = make_float2(o10, o11);
        }
    }
}

__global__ __launch_bounds__(512, 1) void gemm_qkv(
        const float* __restrict__ Aq, const float* __restrict__ Ak,
        const float* __restrict__ Av, const float* __restrict__ Wq,
        const float* __restrict__ Wk, const float* __restrict__ Wv,
        float* Cq, float* Ck, float* Cv) {
    extern __shared__ float sg[];
    const float* A; const float* W; float* C;
    if (blockIdx.z == 0)      { A = Aq; W = Wq; C = Cq; }
    else if (blockIdx.z == 1) { A = Ak; W = Wk; C = Ck; }
    else                      { A = Av; W = Wv; C = Cv; }
    gemm_core(A, W, C, 1, sg);
}

__global__ __launch_bounds__(512, 1) void gemm_out(const float* __restrict__ A,
                                                   const float* __restrict__ W,
                                                   float* __restrict__ C) {
    extern __shared__ float sg[];
    gemm_core(A, W, C, 0, sg);
}

// ===========================================================================
// Causal flash attention, mma.m16n8k8 tf32, register-resident S/P/O.
// 256 threads (8 warps), 128 query rows/CTA (16 per warp), 64-key tiles.
// K/V staged ROW-MAJOR via cp.async (double-buffered); B-fragments read with
// two conflict-free scalar LDS each (K stride 68: bank=4n+k; V stride 72:
// bank=8k+n). q/k/v are tf32-rounded by the projection epilogue -> no cvt
// anywhere in the hot loop. Per-warp skip of fully-masked tiles.
// ===========================================================================
#define APK 68
#define APV 72
#define AKBUF (64*APK)                        // 4352 floats
#define AVBUF (64*APV)                        // 4608 floats
#define A_SMEM ((2*AKBUF + 2*AVBUF)*4)        // 71680 B

__global__ __launch_bounds__(256, 2) void attn_tc() {
    extern __shared__ float sm[];
    const uint32_t sbase = su32(sm);

    const int tid = threadIdx.x;
    const int w = tid >> 5, lane = tid & 31;
    const int g = lane >> 2, q = lane & 3;
    const int b = blockIdx.y / H, h = blockIdx.y % H;
    const int qt = gridDim.x - 1 - blockIdx.x;   // longest CTAs first
    const int qbase = qt * 128;
    const int jmax = 2 * qt + 1;

    const float* Kg = g_k + (size_t)b * T * E + h * D;
    const float* Vg = g_v + (size_t)b * T * E + h * D;

    // Q A-fragments straight from gmem (already tf32; 0.125 scale is exact)
    const float* Q0 = g_q + (size_t)(b * T + qbase + w * 16 + g) * E + h * D;
    uint32_t qa[8][4];
    #pragma unroll
    for (int kc = 0; kc < 8; kc++) {
        qa[kc][0] = __float_as_uint(Q0[kc * 8 + q] * 0.125f);
        qa[kc][1] = __float_as_uint(Q0[(size_t)8 * E + kc * 8 + q] * 0.125f);
        qa[kc][2] = __float_as_uint(Q0[kc * 8 + q + 4] * 0.125f);
        qa[kc][3] = __float_as_uint(Q0[(size_t)8 * E + kc * 8 + q + 4] * 0.125f);
    }

    auto stage = [&](int j) {
        const int buf = j & 1;
        const float* Kt = Kg + (size_t)(j * 64) * E;
        const float* Vt = Vg + (size_t)(j * 64) * E;
        const uint32_t kdst = sbase + buf * (AKBUF * 4);
        const uint32_t vdst = sbase + (2 * AKBUF + buf * AVBUF) * 4;
        #pragma unroll
        for (int t = 0; t < 4; t++) {
            int c = tid + t * 256;               // 0..1023
            int row = c >> 4, ch = c & 15;
            cp16(kdst + (row * APK + ch * 4) * 4, Kt + (size_t)row * E + ch * 4);
            cp16(vdst + (row * APV + ch * 4) * 4, Vt + (size_t)row * E + ch * 4);
        }
        cp_commit();
    };

    float oacc[8][4];
    #pragma unroll
    for (int nt = 0; nt < 8; nt++)
        #pragma unroll
        for (int e = 0; e < 4; e++) oacc[nt][e] = 0.f;

    float m0 = -INFINITY, m1 = -INFINITY, l0 = 0.f, l1 = 0.f;
    const int r0g = qbase + w * 16 + g, r1g = r0g + 8;
    const int wmaxrow = qbase + w * 16 + 15;     // last row this warp owns
    const int s0l = (lane & ~3) | (q >> 1);
    const int s1l = s0l + 2;
    const int kboff = g * APK + q;               // K b-frag base (n=g, k=q)
    const int vboff = q * APV + g;               // V b-frag base (k=q, n=g)

    stage(0);

    for (int j = 0; j <= jmax; j++) {
        __syncthreads();                         // prev compute done everywhere
        if (j < jmax) stage(j + 1);
        else          cp_commit();               // keep wait-group math valid
        cp_wait<1>();                            // this thread's tile-j chunks done
        __syncthreads();                         // all threads' chunks done

        const int kbase = j * 64;
        if (kbase > wmaxrow) continue;           // tile fully masked for warp

        const float* Ks = sm + (j & 1) * AKBUF;
        const float* Vs = sm + 2 * AKBUF + (j & 1) * AVBUF;

        // S = Q @ K^T
        float sacc[8][4];
        #pragma unroll
        for (int nt = 0; nt < 8; nt++) {
            #pragma unroll
            for (int e = 0; e < 4; e++) sacc[nt][e] = 0.f;
            const float* kp = Ks + nt * 8 * APK + kboff;
            #pragma unroll
            for (int kc = 0; kc < 8; kc++) {
                mma8(sacc[nt], qa[kc],
                     __float_as_uint(kp[kc * 8]),
                     __float_as_uint(kp[kc * 8 + 4]));
            }
        }

        // Causal mask (only tiles overlapping the diagonal)
        if (kbase + 63 > r0g) {
            #pragma unroll
            for (int nt = 0; nt < 8; nt++) {
                #pragma unroll
                for (int e = 0; e < 2; e++) {
                    int colg = kbase + nt * 8 + 2 * q + e;
                    if (colg > r0g) sacc[nt][e]     = -INFINITY;
                    if (colg > r1g) sacc[nt][2 + e] = -INFINITY;
                }
            }
        }

        // Online softmax (registers + quad shuffles)
        float mx0 = -INFINITY, mx1 = -INFINITY;
        #pragma unroll
        for (int nt = 0; nt < 8; nt++) {
            mx0 = fmaxf(mx0, fmaxf(sacc[nt][0], sacc[nt][1]));
            mx1 = fmaxf(mx1, fmaxf(sacc[nt][2], sacc[nt][3]));
        }
        mx0 = fmaxf(mx0, __shfl_xor_sync(0xffffffffu, mx0, 1));
        mx0 = fmaxf(mx0, __shfl_xor_sync(0xffffffffu, mx0, 2));
        mx1 = fmaxf(mx1, __shfl_xor_sync(0xffffffffu, mx1, 1));
        mx1 = fmaxf(mx1, __shfl_xor_sync(0xffffffffu, mx1, 2));
        float mn0 = fmaxf(m0, mx0), mn1 = fmaxf(m1, mx1);
        float sc0 = __expf(m0 - mn0), sc1 = __expf(m1 - mn1);

        float s0 = 0.f, s1 = 0.f;
        #pragma unroll
        for (int nt = 0; nt < 8; nt++) {
            float p0 = __expf(sacc[nt][0] - mn0);
            float p1 = __expf(sacc[nt][1] - mn0);
            float p2 = __expf(sacc[nt][2] - mn1);
            float p3 = __expf(sacc[nt][3] - mn1);
            s0 += p0 + p1; s1 += p2 + p3;
            sacc[nt][0] = __uint_as_float(tf32u(p0));
            sacc[nt][1] = __uint_as_float(tf32u(p1));
            sacc[nt][2] = __uint_as_float(tf32u(p2));
            sacc[nt][3] = __uint_as_float(tf32u(p3));
        }
        s0 += __shfl_xor_sync(0xffffffffu, s0, 1);
        s0 += __shfl_xor_sync(0xffffffffu, s0, 2);
        s1 += __shfl_xor_sync(0xffffffffu, s1, 1);
        s1 += __shfl_xor_sync(0xffffffffu, s1, 2);
        l0 = l0 * sc0 + s0; l1 = l1 * sc1 + s1;
        m0 = mn0; m1 = mn1;
        #pragma unroll
        for (int nt = 0; nt < 8; nt++) {
            oacc[nt][0] *= sc0; oacc[nt][1] *= sc0;
            oacc[nt][2] *= sc1; oacc[nt][3] *= sc1;
        }

        // O += P @ V : transpose P acc-layout -> A-layout via quad shuffles
        #pragma unroll
        for (int kc = 0; kc < 8; kc++) {
            uint32_t p0 = __float_as_uint(sacc[kc][0]);
            uint32_t p1 = __float_as_uint(sacc[kc][1]);
            uint32_t p2 = __float_as_uint(sacc[kc][2]);
            uint32_t p3 = __float_as_uint(sacc[kc][3]);
            uint32_t v00 = __shfl_sync(0xffffffffu, p0, s0l);
            uint32_t v01 = __shfl_sync(0xffffffffu, p1, s0l);
            uint32_t v10 = __shfl_sync(0xffffffffu, p2, s0l);
            uint32_t v11 = __shfl_sync(0xffffffffu, p3, s0l);
            uint32_t v20 = __shfl_sync(0xffffffffu, p0, s1l);
            uint32_t v21 = __shfl_sync(0xffffffffu, p1, s1l);
            uint32_t v30 = __shfl_sync(0xffffffffu, p2, s1l);
            uint32_t v31 = __shfl_sync(0xffffffffu, p3, s1l);
            uint32_t pa[4];
            pa[0] = (q & 1) ? v01 : v00;
            pa[1] = (q & 1) ? v11 : v10;
            pa[2] = (q & 1) ? v21 : v20;
            pa[3] = (q & 1) ? v31 : v30;
            const float* vp = Vs + kc * 8 * APV + vboff;
            #pragma unroll
            for (int nt = 0; nt < 8; nt++) {
                mma8(oacc[nt], pa,
                     __float_as_uint(vp[nt * 8]),
                     __float_as_uint(vp[nt * 8 + 4 * APV]));
            }
        }
    }

    const float inv0 = 1.f / l0, inv1 = 1.f / l1;
    float* O0 = g_attn + ((size_t)(b * T + r0g)) * E + h * D;
    float* O1 = g_attn + ((size_t)(b * T + r1g)) * E + h * D;
    #pragma unroll
    for (int nt = 0; nt < 8; nt++) {
        O0[nt * 8 + 2 * q]     = oacc[nt][0] * inv0;
        O0[nt * 8 + 2 * q + 1] = oacc[nt][1] * inv0;
        O1[nt * 8 + 2 * q]     = oacc[nt][2] * inv1;
        O1[nt * 8 + 2 * q + 1] = oacc[nt][3] * inv1;
    }
}

// ===========================================================================
// Inputs: queries, keys, values, mask(unused), Wq, Wk, Wv, Wo
// ===========================================================================
extern "C" void kernel_launch(void* const* d_in, const int* in_sizes, int n_in,
                              void* d_out, int out_size) {
    const float* queries = (const float*)d_in[0];
    const float* keys    = (const float*)d_in[1];
    const float* values  = (const float*)d_in[2];
    const float* Wq      = (const float*)d_in[4];
    const float* Wk      = (const float*)d_in[5];
    const float* Wv      = (const float*)d_in[6];
    const float* Wo      = (const float*)d_in[7];

    float *qp, *kp, *vp, *ap;
    cudaGetSymbolAddress((void**)&qp, g_q);
    cudaGetSymbolAddress((void**)&kp, g_k);
    cudaGetSymbolAddress((void**)&vp, g_v);
    cudaGetSymbolAddress((void**)&ap, g_attn);

    static bool attr_set = false;
    if (!attr_set) {
        cudaFuncSetAttribute(gemm_qkv, cudaFuncAttributeMaxDynamicSharedMemorySize, (int)G_SMEM);
        cudaFuncSetAttribute(gemm_out, cudaFuncAttributeMaxDynamicSharedMemorySize, (int)G_SMEM);
        cudaFuncSetAttribute(attn_tc,  cudaFuncAttributeMaxDynamicSharedMemorySize, (int)A_SMEM);
        attr_set = true;
    }

    dim3 gq(E / NT, (BSZ * T) / MT, 3);     // fused Q/K/V projections
    gemm_qkv<<<gq, 512, G_SMEM>>>(queries, keys, values, Wq, Wk, Wv, qp, kp, vp);

    attn_tc<<<dim3(T / 128, BSZ * H), 256, A_SMEM>>>();

    dim3 gg(E / NT, (BSZ * T) / MT);
    gemm_out<<<gg, 512, G_SMEM>>>(ap, Wo, (float*)d_out);
}

// round 10
// speedup vs baseline: 1.0431x; 1.0431x over previous
#include <cuda_runtime.h>
#include <math.h>
#include <stdint.h>

#define BSZ 2
#define T   2048
#define E   1024
#define H   16
#define D   64

// Scratch (allocation-free rule)
__device__ float g_q[BSZ*T*E];
__device__ float g_k[BSZ*T*E];
__device__ float g_v[BSZ*T*E];
__device__ float g_attn[BSZ*T*E];
// Prepass outputs: tf32-rounded, k-pair-interleaved within 8-groups
__device__ float g_aq[BSZ*T*E];
__device__ float g_ak[BSZ*T*E];
__device__ float g_av[BSZ*T*E];
__device__ float g_wq[E*E];
__device__ float g_wk[E*E];
__device__ float g_wv[E*E];
__device__ float g_wo[E*E];

// ===========================================================================
// Helpers
// ===========================================================================
__device__ __forceinline__ uint32_t su32(const void* p) {
    return (uint32_t)__cvta_generic_to_shared(p);
}
__device__ __forceinline__ float tf32f(float x) {
    uint32_t u; asm("cvt.rna.tf32.f32 %0, %1;" : "=r"(u) : "f"(x));
    return __uint_as_float(u);
}
__device__ __forceinline__ uint32_t tf32u(float x) {
    uint32_t u; asm("cvt.rna.tf32.f32 %0, %1;" : "=r"(u) : "f"(x));
    return u;
}
__device__ __forceinline__ void mma8(float c[4], const uint32_t a[4],
                                     uint32_t b0, uint32_t b1) {
    asm("mma.sync.aligned.m16n8k8.row.col.f32.tf32.tf32.f32 "
        "{%0,%1,%2,%3},{%4,%5,%6,%7},{%8,%9},{%0,%1,%2,%3};"
        : "+f"(c[0]), "+f"(c[1]), "+f"(c[2]), "+f"(c[3])
        : "r"(a[0]), "r"(a[1]), "r"(a[2]), "r"(a[3]), "r"(b0), "r"(b1));
}
__device__ __forceinline__ void cp16(uint32_t dst, const void* src) {
    asm volatile("cp.async.cg.shared.global [%0], [%1], 16;"
                 :: "r"(dst), "l"(src) : "memory");
}
__device__ __forceinline__ void cp_commit() {
    asm volatile("cp.async.commit_group;" ::: "memory");
}
template <int N>
__device__ __forceinline__ void cp_wait() {
    asm volatile("cp.async.wait_group %0;" :: "n"(N) : "memory");
}

// ===========================================================================
// Prepass: tf32-round + pair-interleave 8-k-groups.
// out[0..7] = tf32(in[0]), in[4], in[1], in[5], in[2], in[6], in[3], in[7]
// -> mma fragment {k=q, k=q+4} becomes one contiguous float2 at slot 2q.
// ===========================================================================
struct PPArgs {
    const float* src[7];
    float*       dst[7];
    int          ngrp[7];     // number of 8-float groups
};

__global__ __launch_bounds__(256) void prepass(PPArgs a) {
    const int z = blockIdx.z;
    const int i = blockIdx.x * 256 + threadIdx.x;
    if (i >= a.ngrp[z]) return;
    const float4* s = (const float4*)a.src[z] + (size_t)i * 2;
    float4 lo = s[0], hi = s[1];
    float4 o0 = make_float4(tf32f(lo.x), tf32f(hi.x), tf32f(lo.y), tf32f(hi.y));
    float4 o1 = make_float4(tf32f(lo.z), tf32f(hi.z), tf32f(lo.w), tf32f(hi.w));
    float4* d = (float4*)a.dst[z] + (size_t)i * 2;
    d[0] = o0; d[1] = o1;
}

// ===========================================================================
// tf32 mma.sync GEMM core: C[M,N] = A[M,K] @ W[N,K]^T
// Operands pre-rounded + pair-interleaved -> every fragment is one LDS.64,
// zero cvt in the mainloop. CTA 128x256, 512 thr (16 warps, 32x64 each),
// BK=32, 3-stage cp.async. GPAD=40: LDS.64 banks = 8g+2q, conflict-free.
// mode: 0 = plain fp32 out; 1 = tf32-rounded out (V); 2 = rounded +
// pair-interleaved out (Q,K -> consumed as mma operands by attention).
// ===========================================================================
#define KDIM 1024
#define MT   128
#define NT   256
#define BKF  32
#define GPAD 40
#define G_WOFF (MT*GPAD*4)                   // 20480 B
#define G_STAGE ((MT+NT)*GPAD*4)             // 61440 B
#define G_SMEM (3*G_STAGE)                   // 184320 B

__device__ __forceinline__ void gemm_core(const float* __restrict__ A,
                                          const float* __restrict__ W,
                                          float* __restrict__ C,
                                          int mode, float* sg) {
    const uint32_t sbase = su32(sg);
    const int tid  = threadIdx.x;
    const int wid  = tid >> 5, lane = tid & 31;
    const int g    = lane >> 2, q = lane & 3;
    const int wr   = wid & 3;
    const int wc   = wid >> 2;
    const int bm   = blockIdx.y * MT;
    const int bn   = blockIdx.x * NT;

    const float* gA = A + (size_t)bm * KDIM;
    const float* gW = W + (size_t)bn * KDIM;

    auto cp_stage = [&](int s, int kt) {
        const uint32_t base = sbase + s * G_STAGE;
        const int k0 = kt * BKF;
        #pragma unroll
        for (int i = 0; i < 6; i++) {
            int c = tid + i * 512;
            if (c < 1024) {
                int row = c >> 3, ch = c & 7;
                cp16(base + (row * GPAD + ch * 4) * 4,
                     gA + (size_t)row * KDIM + k0 + ch * 4);
            } else {
                int cc = c - 1024;
                int row = cc >> 3, ch = cc & 7;
                cp16(base + G_WOFF + (row * GPAD + ch * 4) * 4,
                     gW + (size_t)row * KDIM + k0 + ch * 4);
            }
        }
        cp_commit();
    };

    float acc[2][8][4];
    #pragma unroll
    for (int mi = 0; mi < 2; mi++)
        #pragma unroll
        for (int ni = 0; ni < 8; ni++)
            #pragma unroll
            for (int e = 0; e < 4; e++) acc[mi][ni][e] = 0.f;

    cp_stage(0, 0); cp_stage(1, 1);

    const int NKT = KDIM / BKF;   // 32
    int buf = 0;
    for (int kt = 0; kt < NKT; kt++) {
        cp_wait<1>();
        __syncthreads();
        if (kt + 2 < NKT) {
            int nb = buf + 2; if (nb >= 3) nb -= 3;
            cp_stage(nb, kt + 2);
        } else cp_commit();

        const float* As = sg + buf * (G_STAGE / 4);
        const float* Ws = As + MT * GPAD;
        const int m0 = wr * 32, n0 = wc * 64;

        #pragma unroll
        for (int kc = 0; kc < 4; kc++) {
            uint32_t af[2][4];
            #pragma unroll
            for (int mi = 0; mi < 2; mi++) {
                float2 a0 = *(const float2*)&As[(m0 + mi*16 + g) * GPAD + kc*8 + 2*q];
                float2 a1 = *(const float2*)&As[(m0 + mi*16 + g + 8) * GPAD + kc*8 + 2*q];
                af[mi][0] = __float_as_uint(a0.x);
                af[mi][1] = __float_as_uint(a1.x);
                af[mi][2] = __float_as_uint(a0.y);
                af[mi][3] = __float_as_uint(a1.y);
            }
            #pragma unroll
            for (int ni = 0; ni < 8; ni++) {
                float2 bv = *(const float2*)&Ws[(n0 + ni*8 + g) * GPAD + kc*8 + 2*q];
                uint32_t b0 = __float_as_uint(bv.x);
                uint32_t b1 = __float_as_uint(bv.y);
                mma8(acc[0][ni], af[0], b0, b1);
                mma8(acc[1][ni], af[1], b0, b1);
            }
        }
        buf++; if (buf == 3) buf = 0;
    }

    const int s0 = (((2*q)   & 3) << 1) | ((2*q)   >> 2);   // slot of j=2q
    const int s1 = (((2*q+1) & 3) << 1) | ((2*q+1) >> 2);   // slot of j=2q+1
    #pragma unroll
    for (int mi = 0; mi < 2; mi++) {
        const int r0 = bm + wr * 32 + mi * 16 + g;
        #pragma unroll
        for (int ni = 0; ni < 8; ni++) {
            const int colb = bn + wc * 64 + ni * 8;
            if (mode == 2) {
                C[(size_t)r0 * E + colb + s0]       = tf32f(acc[mi][ni][0]);
                C[(size_t)r0 * E + colb + s1]       = tf32f(acc[mi][ni][1]);
                C[(size_t)(r0+8) * E + colb + s0]   = tf32f(acc[mi][ni][2]);
                C[(size_t)(r0+8) * E + colb + s1]   = tf32f(acc[mi][ni][3]);
            } else if (mode == 1) {
                *(float2*)(C + (size_t)r0 * E + colb + 2*q) =
                    make_float2(tf32f(acc[mi][ni][0]), tf32f(acc[mi][ni][1]));
                *(float2*)(C + (size_t)(r0+8) * E + colb + 2*q) =
                    make_float2(tf32f(acc[mi][ni][2]), tf32f(acc[mi][ni][3]));
            } else {
                *(float2*)(C + (size_t)r0 * E + colb + 2*q) =
                    make_float2(acc[mi][ni][0], acc[mi][ni][1]);
                *(float2*)(C + (size_t)(r0+8) * E + colb + 2*q) =
                    make_float2(acc[mi][ni][2], acc[mi][ni][3]);
            }
        }
    }
}

__global__ __launch_bounds__(512, 1) void gemm_qkv(float* Cq, float* Ck, float* Cv) {
    extern __shared__ float sg[];
    if (blockIdx.z == 0)      gemm_core(g_aq, g_wq, Cq, 2, sg);
    else if (blockIdx.z == 1) gemm_core(g_ak, g_wk, Ck, 2, sg);
    else                      gemm_core(g_av, g_wv, Cv, 1, sg);
}

__global__ __launch_bounds__(512, 1) void gemm_out(const float* __restrict__ A,
                                                   float* __restrict__ C) {
    extern __shared__ float sg[];
    gemm_core(A, g_wo, C, 0, sg);
}

// ===========================================================================
// Causal flash attention. g_q/g_k are tf32 + pair-interleaved -> Q a-frags
// are LDG.64, K b-frags are single LDS.64 (APK=72: banks 8g+2q, clean).
// V plain rounded row-major (APV=72: banks 8q+g, clean). 256 thr, 128 q-rows,
// 64-key tiles, double-buffered cp.async, register S/P/O, per-warp skip.
// Epilogue writes g_attn rounded + pair-interleaved for gemm_out.
// ===========================================================================
#define APK 72
#define APV 72
#define AKBUF (64*APK)
#define AVBUF (64*APV)
#define A_SMEM ((2*AKBUF + 2*AVBUF)*4)       // 73728 B

__global__ __launch_bounds__(256, 2) void attn_tc() {
    extern __shared__ float sm[];
    const uint32_t sbase = su32(sm);

    const int tid = threadIdx.x;
    const int w = tid >> 5, lane = tid & 31;
    const int g = lane >> 2, q = lane & 3;
    const int b = blockIdx.y / H, h = blockIdx.y % H;
    const int qt = gridDim.x - 1 - blockIdx.x;
    const int qbase = qt * 128;
    const int jmax = 2 * qt + 1;

    const float* Kg = g_k + (size_t)b * T * E + h * D;
    const float* Vg = g_v + (size_t)b * T * E + h * D;

    // Q a-frags: pair-interleaved gmem -> LDG.64 (0.125 scale exact on tf32)
    const float* Q0 = g_q + (size_t)(b * T + qbase + w * 16 + g) * E + h * D;
    uint32_t qa[8][4];
    #pragma unroll
    for (int kc = 0; kc < 8; kc++) {
        float2 x0 = *(const float2*)&Q0[kc * 8 + 2 * q];
        float2 x1 = *(const float2*)&Q0[(size_t)8 * E + kc * 8 + 2 * q];
        qa[kc][0] = __float_as_uint(x0.x * 0.125f);
        qa[kc][1] = __float_as_uint(x1.x * 0.125f);
        qa[kc][2] = __float_as_uint(x0.y * 0.125f);
        qa[kc][3] = __float_as_uint(x1.y * 0.125f);
    }

    auto stage = [&](int j) {
        const int buf = j & 1;
        const float* Kt = Kg + (size_t)(j * 64) * E;
        const float* Vt = Vg + (size_t)(j * 64) * E;
        const uint32_t kdst = sbase + buf * (AKBUF * 4);
        const uint32_t vdst = sbase + (2 * AKBUF + buf * AVBUF) * 4;
        #pragma unroll
        for (int t = 0; t < 4; t++) {
            int c = tid + t * 256;
            int row = c >> 4, ch = c & 15;
            cp16(kdst + (row * APK + ch * 4) * 4, Kt + (size_t)row * E + ch * 4);
            cp16(vdst + (row * APV + ch * 4) * 4, Vt + (size_t)row * E + ch * 4);
        }
        cp_commit();
    };

    float oacc[8][4];
    #pragma unroll
    for (int nt = 0; nt < 8; nt++)
        #pragma unroll
        for (int e = 0; e < 4; e++) oacc[nt][e] = 0.f;

    float m0 = -INFINITY, m1 = -INFINITY, l0 = 0.f, l1 = 0.f;
    const int r0g = qbase + w * 16 + g, r1g = r0g + 8;
    const int wmaxrow = qbase + w * 16 + 15;
    const int s0l = (lane & ~3) | (q >> 1);
    const int s1l = s0l + 2;

    stage(0);

    for (int j = 0; j <= jmax; j++) {
        __syncthreads();
        if (j < jmax) stage(j + 1);
        else          cp_commit();
        cp_wait<1>();
        __syncthreads();

        const int kbase = j * 64;
        if (kbase > wmaxrow) continue;

        const float* Ks = sm + (j & 1) * AKBUF;
        const float* Vs = sm + 2 * AKBUF + (j & 1) * AVBUF;

        // S = Q @ K^T  (K b-frag: one LDS.64)
        float sacc[8][4];
        #pragma unroll
        for (int nt = 0; nt < 8; nt++) {
            #pragma unroll
            for (int e = 0; e < 4; e++) sacc[nt][e] = 0.f;
            const float* kp = Ks + (nt * 8 + g) * APK + 2 * q;
            #pragma unroll
            for (int kc = 0; kc < 8; kc++) {
                float2 kb = *(const float2*)&kp[kc * 8];
                mma8(sacc[nt], qa[kc],
                     __float_as_uint(kb.x), __float_as_uint(kb.y));
            }
        }

        if (kbase + 63 > r0g) {
            #pragma unroll
            for (int nt = 0; nt < 8; nt++) {
                #pragma unroll
                for (int e = 0; e < 2; e++) {
                    int colg = kbase + nt * 8 + 2 * q + e;
                    if (colg > r0g) sacc[nt][e]     = -INFINITY;
                    if (colg > r1g) sacc[nt][2 + e] = -INFINITY;
                }
            }
        }

        float mx0 = -INFINITY, mx1 = -INFINITY;
        #pragma unroll
        for (int nt = 0; nt < 8; nt++) {
            mx0 = fmaxf(mx0, fmaxf(sacc[nt][0], sacc[nt][1]));
            mx1 = fmaxf(mx1, fmaxf(sacc[nt][2], sacc[nt][3]));
        }
        mx0 = fmaxf(mx0, __shfl_xor_sync(0xffffffffu, mx0, 1));
        mx0 = fmaxf(mx0, __shfl_xor_sync(0xffffffffu, mx0, 2));
        mx1 = fmaxf(mx1, __shfl_xor_sync(0xffffffffu, mx1, 1));
        mx1 = fmaxf(mx1, __shfl_xor_sync(0xffffffffu, mx1, 2));
        float mn0 = fmaxf(m0, mx0), mn1 = fmaxf(m1, mx1);
        float sc0 = __expf(m0 - mn0), sc1 = __expf(m1 - mn1);

        float s0 = 0.f, s1 = 0.f;
        #pragma unroll
        for (int nt = 0; nt < 8; nt++) {
            float p0 = __expf(sacc[nt][0] - mn0);
            float p1 = __expf(sacc[nt][1] - mn0);
            float p2 = __expf(sacc[nt][2] - mn1);
            float p3 = __expf(sacc[nt][3] - mn1);
            s0 += p0 + p1; s1 += p2 + p3;
            sacc[nt][0] = __uint_as_float(tf32u(p0));
            sacc[nt][1] = __uint_as_float(tf32u(p1));
            sacc[nt][2] = __uint_as_float(tf32u(p2));
            sacc[nt][3] = __uint_as_float(tf32u(p3));
        }
        s0 += __shfl_xor_sync(0xffffffffu, s0, 1);
        s0 += __shfl_xor_sync(0xffffffffu, s0, 2);
        s1 += __shfl_xor_sync(0xffffffffu, s1, 1);
        s1 += __shfl_xor_sync(0xffffffffu, s1, 2);
        l0 = l0 * sc0 + s0; l1 = l1 * sc1 + s1;
        m0 = mn0; m1 = mn1;
        #pragma unroll
        for (int nt = 0; nt < 8; nt++) {
            oacc[nt][0] *= sc0; oacc[nt][1] *= sc0;
            oacc[nt][2] *= sc1; oacc[nt][3] *= sc1;
        }

        #pragma unroll
        for (int kc = 0; kc < 8; kc++) {
            uint32_t p0 = __float_as_uint(sacc[kc][0]);
            uint32_t p1 = __float_as_uint(sacc[kc][1]);
            uint32_t p2 = __float_as_uint(sacc[kc][2]);
            uint32_t p3 = __float_as_uint(sacc[kc][3]);
            uint32_t v00 = __shfl_sync(0xffffffffu, p0, s0l);
            uint32_t v01 = __shfl_sync(0xffffffffu, p1, s0l);
            uint32_t v10 = __shfl_sync(0xffffffffu, p2, s0l);
            uint32_t v11 = __shfl_sync(0xffffffffu, p3, s0l);
            uint32_t v20 = __shfl_sync(0xffffffffu, p0, s1l);
            uint32_t v21 = __shfl_sync(0xffffffffu, p1, s1l);
            uint32_t v30 = __shfl_sync(0xffffffffu, p2, s1l);
            uint32_t v31 = __shfl_sync(0xffffffffu, p3, s1l);
            uint32_t pa[4];
            pa[0] = (q & 1) ? v01 : v00;
            pa[1] = (q & 1) ? v11 : v10;
            pa[2] = (q & 1) ? v21 : v20;
            pa[3] = (q & 1) ? v31 : v30;
            const float* vp = Vs + (kc * 8 + q) * APV + g;
            #pragma unroll
            for (int nt = 0; nt < 8; nt++) {
                mma8(oacc[nt], pa,
                     __float_as_uint(vp[nt * 8]),
                     __float_as_uint(vp[nt * 8 + 4 * APV]));
            }
        }
    }

    // Epilogue: rounded + pair-interleaved for gemm_out's A path
    const float inv0 = 1.f / l0, inv1 = 1.f / l1;
    const int es0 = (((2*q)   & 3) << 1) | ((2*q)   >> 2);
    const int es1 = (((2*q+1) & 3) << 1) | ((2*q+1) >> 2);
    float* O0 = g_attn + ((size_t)(b * T + r0g)) * E + h * D;
    float* O1 = g_attn + ((size_t)(b * T + r1g)) * E + h * D;
    #pragma unroll
    for (int nt = 0; nt < 8; nt++) {
        O0[nt * 8 + es0] = tf32f(oacc[nt][0] * inv0);
        O0[nt * 8 + es1] = tf32f(oacc[nt][1] * inv0);
        O1[nt * 8 + es0] = tf32f(oacc[nt][2] * inv1);
        O1[nt * 8 + es1] = tf32f(oacc[nt][3] * inv1);
    }
}

// ===========================================================================
// Inputs: queries, keys, values, mask(unused), Wq, Wk, Wv, Wo
// ===========================================================================
extern "C" void kernel_launch(void* const* d_in, const int* in_sizes, int n_in,
                              void* d_out, int out_size) {
    const float* queries = (const float*)d_in[0];
    const float* keys    = (const float*)d_in[1];
    const float* values  = (const float*)d_in[2];
    const float* Wq      = (const float*)d_in[4];
    const float* Wk      = (const float*)d_in[5];
    const float* Wv      = (const float*)d_in[6];
    const float* Wo      = (const float*)d_in[7];

    float *qp, *kp, *vp, *ap;
    float *aq, *ak, *av, *wq, *wk, *wv, *wo;
    cudaGetSymbolAddress((void**)&qp, g_q);
    cudaGetSymbolAddress((void**)&kp, g_k);
    cudaGetSymbolAddress((void**)&vp, g_v);
    cudaGetSymbolAddress((void**)&ap, g_attn);
    cudaGetSymbolAddress((void**)&aq, g_aq);
    cudaGetSymbolAddress((void**)&ak, g_ak);
    cudaGetSymbolAddress((void**)&av, g_av);
    cudaGetSymbolAddress((void**)&wq, g_wq);
    cudaGetSymbolAddress((void**)&wk, g_wk);
    cudaGetSymbolAddress((void**)&wv, g_wv);
    cudaGetSymbolAddress((void**)&wo, g_wo);

    static bool attr_set = false;
    if (!attr_set) {
        cudaFuncSetAttribute(gemm_qkv, cudaFuncAttributeMaxDynamicSharedMemorySize, (int)G_SMEM);
        cudaFuncSetAttribute(gemm_out, cudaFuncAttributeMaxDynamicSharedMemorySize, (int)G_SMEM);
        cudaFuncSetAttribute(attn_tc,  cudaFuncAttributeMaxDynamicSharedMemorySize, (int)A_SMEM);
        attr_set = true;
    }

    PPArgs pa;
    const int NG_IN = BSZ * T * E / 8;   // 524288
    const int NG_W  = E * E / 8;         // 131072
    pa.src[0] = queries; pa.dst[0] = aq; pa.ngrp[0] = NG_IN;
    pa.src[1] = keys;    pa.dst[1] = ak; pa.ngrp[1] = NG_IN;
    pa.src[2] = values;  pa.dst[2] = av; pa.ngrp[2] = NG_IN;
    pa.src[3] = Wq;      pa.dst[3] = wq; pa.ngrp[3] = NG_W;
    pa.src[4] = Wk;      pa.dst[4] = wk; pa.ngrp[4] = NG_W;
    pa.src[5] = Wv;      pa.dst[5] = wv; pa.ngrp[5] = NG_W;
    pa.src[6] = Wo;      pa.dst[6] = wo; pa.ngrp[6] = NG_W;
    prepass<<<dim3(NG_IN / 256, 1, 7), 256>>>(pa);

    dim3 gq(E / NT, (BSZ * T) / MT, 3);
    gemm_qkv<<<gq, 512, G_SMEM>>>(qp, kp, vp);

    attn_tc<<<dim3(T / 128, BSZ * H), 256, A_SMEM>>>();

    dim3 gg(E / NT, (BSZ * T) / MT);
    gemm_out<<<gg, 512, G_SMEM>>>(ap, (float*)d_out);
}

// round 11
// speedup vs baseline: 1.4190x; 1.3604x over previous
#include <cuda_runtime.h>
#include <cuda_fp16.h>
#include <math.h>
#include <stdint.h>

#define BSZ 2
#define T   2048
#define E   1024
#define H   16
#define D   64

// fp32 intermediates for attention (tf32 path)
__device__ float g_q[BSZ*T*E];
__device__ float g_k[BSZ*T*E];
__device__ float g_v[BSZ*T*E];
// fp16 pair-interleaved GEMM operands
__device__ __half g_attn[BSZ*T*E];      // written by attn, read by gemm_out
__device__ __half g_haq[BSZ*T*E];
__device__ __half g_hak[BSZ*T*E];
__device__ __half g_hav[BSZ*T*E];
__device__ __half g_hwq[E*E];
__device__ __half g_hwk[E*E];
__device__ __half g_hwv[E*E];
__device__ __half g_hwo[E*E];

// ===========================================================================
// Helpers
// ===========================================================================
__device__ __forceinline__ uint32_t su32(const void* p) {
    return (uint32_t)__cvta_generic_to_shared(p);
}
__device__ __forceinline__ float tf32f(float x) {
    uint32_t u; asm("cvt.rna.tf32.f32 %0, %1;" : "=r"(u) : "f"(x));
    return __uint_as_float(u);
}
__device__ __forceinline__ uint32_t tf32u(float x) {
    uint32_t u; asm("cvt.rna.tf32.f32 %0, %1;" : "=r"(u) : "f"(x));
    return u;
}
__device__ __forceinline__ void mma8(float c[4], const uint32_t a[4],
                                     uint32_t b0, uint32_t b1) {
    asm("mma.sync.aligned.m16n8k8.row.col.f32.tf32.tf32.f32 "
        "{%0,%1,%2,%3},{%4,%5,%6,%7},{%8,%9},{%0,%1,%2,%3};"
        : "+f"(c[0]), "+f"(c[1]), "+f"(c[2]), "+f"(c[3])
        : "r"(a[0]), "r"(a[1]), "r"(a[2]), "r"(a[3]), "r"(b0), "r"(b1));
}
__device__ __forceinline__ void mma16(float c[4], uint32_t a0, uint32_t a1,
                                      uint32_t a2, uint32_t a3,
                                      uint32_t b0, uint32_t b1) {
    asm("mma.sync.aligned.m16n8k16.row.col.f32.f16.f16.f32 "
        "{%0,%1,%2,%3},{%4,%5,%6,%7},{%8,%9},{%0,%1,%2,%3};"
        : "+f"(c[0]), "+f"(c[1]), "+f"(c[2]), "+f"(c[3])
        : "r"(a0), "r"(a1), "r"(a2), "r"(a3), "r"(b0), "r"(b1));
}
__device__ __forceinline__ void cp16(uint32_t dst, const void* src) {
    asm volatile("cp.async.cg.shared.global [%0], [%1], 16;"
                 :: "r"(dst), "l"(src) : "memory");
}
__device__ __forceinline__ void cp_commit() {
    asm volatile("cp.async.commit_group;" ::: "memory");
}
template <int N>
__device__ __forceinline__ void cp_wait() {
    asm volatile("cp.async.wait_group %0;" :: "n"(N) : "memory");
}
__device__ __forceinline__ uint32_t h2u(__half2 h) {
    return *(uint32_t*)&h;
}

// ===========================================================================
// Prepass: fp32 -> fp16, pair-interleaved within each 16-element k-group:
// out halves = in{0,1, 8,9, 2,3, 10,11, 4,5, 12,13, 6,7, 14,15}
// -> m16n8k16 fragment {k=2q..2q+1, k=2q+8..2q+9} is one contiguous LDS.64.
// ===========================================================================
struct PPArgs {
    const float* src[7];
    __half*      dst[7];
    int          ngrp[7];     // number of 16-float groups
};

__global__ __launch_bounds__(256) void prepass(PPArgs a) {
    const int z = blockIdx.z;
    const int i = blockIdx.x * 256 + threadIdx.x;
    if (i >= a.ngrp[z]) return;
    const float4* s = (const float4*)a.src[z] + (size_t)i * 4;
    float4 f0 = s[0], f1 = s[1], f2 = s[2], f3 = s[3];
    uint4 o0, o1;
    o0.x = h2u(__floats2half2_rn(f0.x, f0.y));   // in 0,1
    o0.y = h2u(__floats2half2_rn(f2.x, f2.y));   // in 8,9
    o0.z = h2u(__floats2half2_rn(f0.z, f0.w));   // in 2,3
    o0.w = h2u(__floats2half2_rn(f2.z, f2.w));   // in 10,11
    o1.x = h2u(__floats2half2_rn(f1.x, f1.y));   // in 4,5
    o1.y = h2u(__floats2half2_rn(f3.x, f3.y));   // in 12,13
    o1.z = h2u(__floats2half2_rn(f1.z, f1.w));   // in 6,7
    o1.w = h2u(__floats2half2_rn(f3.z, f3.w));   // in 14,15
    uint4* d = (uint4*)(a.dst[z] + (size_t)i * 16);
    d[0] = o0; d[1] = o1;
}

// ===========================================================================
// fp16 mma.m16n8k16 GEMM core: C[M,N] = A[M,K] @ W[N,K]^T, fp32 accum.
// CTA 128x256, 512 thr (16 warps, warp 32x64), BK=64 halves, 3-stage cp.async.
// Operands pre-interleaved: every fragment = one LDS.64 (row stride 160 B,
// word-stride 40 === 8 mod 32 -> conflict-free). Zero cvt in mainloop.
// mode: 0 = fp32 out; 1 = tf32-rounded out (V); 2 = tf32-rounded +
// float-pair-interleaved out (Q,K for the attention tf32 mma path).
// ===========================================================================
#define KDIM 1024
#define MT   128
#define NT   256
#define BKH  64                               // k-halves per stage
#define HSTRIDE 80                            // halves per smem row (160 B)
#define G_WOFFH (MT*HSTRIDE)                  // A region = 128 rows
#define G_STAGEH ((MT+NT)*HSTRIDE)            // 30720 halves = 61440 B
#define G_SMEM (3*G_STAGEH*2)                 // 184320 B

__device__ __forceinline__ void gemm_core(const __half* __restrict__ A,
                                          const __half* __restrict__ W,
                                          float* __restrict__ C,
                                          int mode, __half* sg) {
    const uint32_t sbase = su32(sg);
    const int tid  = threadIdx.x;
    const int wid  = tid >> 5, lane = tid & 31;
    const int g    = lane >> 2, q = lane & 3;
    const int wr   = wid & 3;
    const int wc   = wid >> 2;
    const int bm   = blockIdx.y * MT;
    const int bn   = blockIdx.x * NT;

    const __half* gA = A + (size_t)bm * KDIM;
    const __half* gW = W + (size_t)bn * KDIM;

    auto cp_stage = [&](int s, int kt) {
        const uint32_t base = sbase + s * (G_STAGEH * 2);
        const int k0 = kt * BKH;
        #pragma unroll
        for (int i = 0; i < 6; i++) {
            int c = tid + i * 512;                   // 0..3071
            if (c < 1024) {                           // A: 128 rows x 8 chunks
                int row = c >> 3, ch = c & 7;
                cp16(base + row * (HSTRIDE*2) + ch * 16,
                     gA + (size_t)row * KDIM + k0 + ch * 8);
            } else {                                  // W: 256 rows x 8 chunks
                int cc = c - 1024;
                int row = cc >> 3, ch = cc & 7;
                cp16(base + G_WOFFH*2 + row * (HSTRIDE*2) + ch * 16,
                     gW + (size_t)row * KDIM + k0 + ch * 8);
            }
        }
        cp_commit();
    };

    float acc[2][8][4];
    #pragma unroll
    for (int mi = 0; mi < 2; mi++)
        #pragma unroll
        for (int ni = 0; ni < 8; ni++)
            #pragma unroll
            for (int e = 0; e < 4; e++) acc[mi][ni][e] = 0.f;

    cp_stage(0, 0); cp_stage(1, 1);

    const int NKT = KDIM / BKH;   // 16
    int buf = 0;
    for (int kt = 0; kt < NKT; kt++) {
        cp_wait<1>();
        __syncthreads();
        if (kt + 2 < NKT) {
            int nb = buf + 2; if (nb >= 3) nb -= 3;
            cp_stage(nb, kt + 2);
        } else cp_commit();

        const __half* As = sg + buf * G_STAGEH;
        const __half* Ws = As + G_WOFFH;
        const int m0 = wr * 32, n0 = wc * 64;

        #pragma unroll
        for (int kc = 0; kc < 4; kc++) {           // 4 x K=16
            const int hoff = kc * 16 + 4 * q;      // half offset of fragment
            uint2 ra[2], rb[2];
            #pragma unroll
            for (int mi = 0; mi < 2; mi++) {
                ra[mi] = *(const uint2*)&As[(m0 + mi*16 + g) * HSTRIDE + hoff];
                rb[mi] = *(const uint2*)&As[(m0 + mi*16 + g + 8) * HSTRIDE + hoff];
            }
            #pragma unroll
            for (int ni = 0; ni < 8; ni++) {
                uint2 wv = *(const uint2*)&Ws[(n0 + ni*8 + g) * HSTRIDE + hoff];
                mma16(acc[0][ni], ra[0].x, rb[0].x, ra[0].y, rb[0].y, wv.x, wv.y);
                mma16(acc[1][ni], ra[1].x, rb[1].x, ra[1].y, rb[1].y, wv.x, wv.y);
            }
        }
        buf++; if (buf == 3) buf = 0;
    }

    const int s0 = (((2*q)   & 3) << 1) | ((2*q)   >> 2);
    const int s1 = (((2*q+1) & 3) << 1) | ((2*q+1) >> 2);
    #pragma unroll
    for (int mi = 0; mi < 2; mi++) {
        const int r0 = bm + wr * 32 + mi * 16 + g;
        #pragma unroll
        for (int ni = 0; ni < 8; ni++) {
            const int colb = bn + wc * 64 + ni * 8;
            if (mode == 2) {
                C[(size_t)r0 * E + colb + s0]     = tf32f(acc[mi][ni][0]);
                C[(size_t)r0 * E + colb + s1]     = tf32f(acc[mi][ni][1]);
                C[(size_t)(r0+8) * E + colb + s0] = tf32f(acc[mi][ni][2]);
                C[(size_t)(r0+8) * E + colb + s1] = tf32f(acc[mi][ni][3]);
            } else if (mode == 1) {
                *(float2*)(C + (size_t)r0 * E + colb + 2*q) =
                    make_float2(tf32f(acc[mi][ni][0]), tf32f(acc[mi][ni][1]));
                *(float2*)(C + (size_t)(r0+8) * E + colb + 2*q) =
                    make_float2(tf32f(acc[mi][ni][2]), tf32f(acc[mi][ni][3]));
            } else {
                *(float2*)(C + (size_t)r0 * E + colb + 2*q) =
                    make_float2(acc[mi][ni][0], acc[mi][ni][1]);
                *(float2*)(C + (size_t)(r0+8) * E + colb + 2*q) =
                    make_float2(acc[mi][ni][2], acc[mi][ni][3]);
            }
        }
    }
}

__global__ __launch_bounds__(512, 1) void gemm_qkv(float* Cq, float* Ck, float* Cv) {
    extern __shared__ __half sg[];
    if (blockIdx.z == 0)      gemm_core(g_haq, g_hwq, Cq, 2, sg);
    else if (blockIdx.z == 1) gemm_core(g_hak, g_hwk, Ck, 2, sg);
    else                      gemm_core(g_hav, g_hwv, Cv, 1, sg);
}

__global__ __launch_bounds__(512, 1) void gemm_out(float* __restrict__ C) {
    extern __shared__ __half sg[];
    gemm_core(g_attn, g_hwo, C, 0, sg);
}

// ===========================================================================
// Causal flash attention, tf32 mma (unchanged math). Epilogue now writes
// g_attn as fp16 in the GEMM's pair-interleaved layout (one half2 per nt).
// ===========================================================================
#define APK 72
#define APV 72
#define AKBUF (64*APK)
#define AVBUF (64*APV)
#define A_SMEM ((2*AKBUF + 2*AVBUF)*4)       // 73728 B

__global__ __launch_bounds__(256, 2) void attn_tc() {
    extern __shared__ float sm[];
    const uint32_t sbase = su32(sm);

    const int tid = threadIdx.x;
    const int w = tid >> 5, lane = tid & 31;
    const int g = lane >> 2, q = lane & 3;
    const int b = blockIdx.y / H, h = blockIdx.y % H;
    const int qt = gridDim.x - 1 - blockIdx.x;
    const int qbase = qt * 128;
    const int jmax = 2 * qt + 1;

    const float* Kg = g_k + (size_t)b * T * E + h * D;
    const float* Vg = g_v + (size_t)b * T * E + h * D;

    const float* Q0 = g_q + (size_t)(b * T + qbase + w * 16 + g) * E + h * D;
    uint32_t qa[8][4];
    #pragma unroll
    for (int kc = 0; kc < 8; kc++) {
        float2 x0 = *(const float2*)&Q0[kc * 8 + 2 * q];
        float2 x1 = *(const float2*)&Q0[(size_t)8 * E + kc * 8 + 2 * q];
        qa[kc][0] = __float_as_uint(x0.x * 0.125f);
        qa[kc][1] = __float_as_uint(x1.x * 0.125f);
        qa[kc][2] = __float_as_uint(x0.y * 0.125f);
        qa[kc][3] = __float_as_uint(x1.y * 0.125f);
    }

    auto stage = [&](int j) {
        const int buf = j & 1;
        const float* Kt = Kg + (size_t)(j * 64) * E;
        const float* Vt = Vg + (size_t)(j * 64) * E;
        const uint32_t kdst = sbase + buf * (AKBUF * 4);
        const uint32_t vdst = sbase + (2 * AKBUF + buf * AVBUF) * 4;
        #pragma unroll
        for (int t = 0; t < 4; t++) {
            int c = tid + t * 256;
            int row = c >> 4, ch = c & 15;
            cp16(kdst + (row * APK + ch * 4) * 4, Kt + (size_t)row * E + ch * 4);
            cp16(vdst + (row * APV + ch * 4) * 4, Vt + (size_t)row * E + ch * 4);
        }
        cp_commit();
    };

    float oacc[8][4];
    #pragma unroll
    for (int nt = 0; nt < 8; nt++)
        #pragma unroll
        for (int e = 0; e < 4; e++) oacc[nt][e] = 0.f;

    float m0 = -INFINITY, m1 = -INFINITY, l0 = 0.f, l1 = 0.f;
    const int r0g = qbase + w * 16 + g, r1g = r0g + 8;
    const int wmaxrow = qbase + w * 16 + 15;
    const int s0l = (lane & ~3) | (q >> 1);
    const int s1l = s0l + 2;

    stage(0);

    for (int j = 0; j <= jmax; j++) {
        __syncthreads();
        if (j < jmax) stage(j + 1);
        else          cp_commit();
        cp_wait<1>();
        __syncthreads();

        const int kbase = j * 64;
        if (kbase > wmaxrow) continue;

        const float* Ks = sm + (j & 1) * AKBUF;
        const float* Vs = sm + 2 * AKBUF + (j & 1) * AVBUF;

        float sacc[8][4];
        #pragma unroll
        for (int nt = 0; nt < 8; nt++) {
            #pragma unroll
            for (int e = 0; e < 4; e++) sacc[nt][e] = 0.f;
            const float* kp = Ks + (nt * 8 + g) * APK + 2 * q;
            #pragma unroll
            for (int kc = 0; kc < 8; kc++) {
                float2 kb = *(const float2*)&kp[kc * 8];
                mma8(sacc[nt], qa[kc],
                     __float_as_uint(kb.x), __float_as_uint(kb.y));
            }
        }

        if (kbase + 63 > r0g) {
            #pragma unroll
            for (int nt = 0; nt < 8; nt++) {
                #pragma unroll
                for (int e = 0; e < 2; e++) {
                    int colg = kbase + nt * 8 + 2 * q + e;
                    if (colg > r0g) sacc[nt][e]     = -INFINITY;
                    if (colg > r1g) sacc[nt][2 + e] = -INFINITY;
                }
            }
        }

        float mx0 = -INFINITY, mx1 = -INFINITY;
        #pragma unroll
        for (int nt = 0; nt < 8; nt++) {
            mx0 = fmaxf(mx0, fmaxf(sacc[nt][0], sacc[nt][1]));
            mx1 = fmaxf(mx1, fmaxf(sacc[nt][2], sacc[nt][3]));
        }
        mx0 = fmaxf(mx0, __shfl_xor_sync(0xffffffffu, mx0, 1));
        mx0 = fmaxf(mx0, __shfl_xor_sync(0xffffffffu, mx0, 2));
        mx1 = fmaxf(mx1, __shfl_xor_sync(0xffffffffu, mx1, 1));
        mx1 = fmaxf(mx1, __shfl_xor_sync(0xffffffffu, mx1, 2));
        float mn0 = fmaxf(m0, mx0), mn1 = fmaxf(m1, mx1);
        float sc0 = __expf(m0 - mn0), sc1 = __expf(m1 - mn1);

        float s0 = 0.f, s1 = 0.f;
        #pragma unroll
        for (int nt = 0; nt < 8; nt++) {
            float p0 = __expf(sacc[nt][0] - mn0);
            float p1 = __expf(sacc[nt][1] - mn0);
            float p2 = __expf(sacc[nt][2] - mn1);
            float p3 = __expf(sacc[nt][3] - mn1);
            s0 += p0 + p1; s1 += p2 + p3;
            sacc[nt][0] = __uint_as_float(tf32u(p0));
            sacc[nt][1] = __uint_as_float(tf32u(p1));
            sacc[nt][2] = __uint_as_float(tf32u(p2));
            sacc[nt][3] = __uint_as_float(tf32u(p3));
        }
        s0 += __shfl_xor_sync(0xffffffffu, s0, 1);
        s0 += __shfl_xor_sync(0xffffffffu, s0, 2);
        s1 += __shfl_xor_sync(0xffffffffu, s1, 1);
        s1 += __shfl_xor_sync(0xffffffffu, s1, 2);
        l0 = l0 * sc0 + s0; l1 = l1 * sc1 + s1;
        m0 = mn0; m1 = mn1;
        #pragma unroll
        for (int nt = 0; nt < 8; nt++) {
            oacc[nt][0] *= sc0; oacc[nt][1] *= sc0;
            oacc[nt][2] *= sc1; oacc[nt][3] *= sc1;
        }

        #pragma unroll
        for (int kc = 0; kc < 8; kc++) {
            uint32_t p0 = __float_as_uint(sacc[kc][0]);
            uint32_t p1 = __float_as_uint(sacc[kc][1]);
            uint32_t p2 = __float_as_uint(sacc[kc][2]);
            uint32_t p3 = __float_as_uint(sacc[kc][3]);
            uint32_t v00 = __shfl_sync(0xffffffffu, p0, s0l);
            uint32_t v01 = __shfl_sync(0xffffffffu, p1, s0l);
            uint32_t v10 = __shfl_sync(0xffffffffu, p2, s0l);
            uint32_t v11 = __shfl_sync(0xffffffffu, p3, s0l);
            uint32_t v20 = __shfl_sync(0xffffffffu, p0, s1l);
            uint32_t v21 = __shfl_sync(0xffffffffu, p1, s1l);
            uint32_t v30 = __shfl_sync(0xffffffffu, p2, s1l);
            uint32_t v31 = __shfl_sync(0xffffffffu, p3, s1l);
            uint32_t pa[4];
            pa[0] = (q & 1) ? v01 : v00;
            pa[1] = (q & 1) ? v11 : v10;
            pa[2] = (q & 1) ? v21 : v20;
            pa[3] = (q & 1) ? v31 : v30;
            const float* vp = Vs + (kc * 8 + q) * APV + g;
            #pragma unroll
            for (int nt = 0; nt < 8; nt++) {
                mma8(oacc[nt], pa,
                     __float_as_uint(vp[nt * 8]),
                     __float_as_uint(vp[nt * 8 + 4 * APV]));
            }
        }
    }

    // Epilogue: fp16, pair-interleaved for gemm_out's fp16 A path.
    // element (nt*8 + 2q + e) lands at half-index
    //   (nt>>1)*16 + (2q + (nt&1))*2 + e   within the head's 64-half block.
    const float inv0 = 1.f / l0, inv1 = 1.f / l1;
    __half* O0 = g_attn + ((size_t)(b * T + r0g)) * E + h * D;
    __half* O1 = g_attn + ((size_t)(b * T + r1g)) * E + h * D;
    #pragma unroll
    for (int nt = 0; nt < 8; nt++) {
        int idx = ((nt >> 1) << 4) + 4 * q + 2 * (nt & 1);
        *(__half2*)(O0 + idx) = __floats2half2_rn(oacc[nt][0] * inv0,
                                                  oacc[nt][1] * inv0);
        *(__half2*)(O1 + idx) = __floats2half2_rn(oacc[nt][2] * inv1,
                                                  oacc[nt][3] * inv1);
    }
}

// ===========================================================================
// Inputs: queries, keys, values, mask(unused), Wq, Wk, Wv, Wo
// ===========================================================================
extern "C" void kernel_launch(void* const* d_in, const int* in_sizes, int n_in,
                              void* d_out, int out_size) {
    const float* queries = (const float*)d_in[0];
    const float* keys    = (const float*)d_in[1];
    const float* values  = (const float*)d_in[2];
    const float* Wq      = (const float*)d_in[4];
    const float* Wk      = (const float*)d_in[5];
    const float* Wv      = (const float*)d_in[6];
    const float* Wo      = (const float*)d_in[7];

    float *qp, *kp, *vp;
    __half *haq, *hak, *hav, *hwq, *hwk, *hwv, *hwo;
    cudaGetSymbolAddress((void**)&qp,  g_q);
    cudaGetSymbolAddress((void**)&kp,  g_k);
    cudaGetSymbolAddress((void**)&vp,  g_v);
    cudaGetSymbolAddress((void**)&haq, g_haq);
    cudaGetSymbolAddress((void**)&hak, g_hak);
    cudaGetSymbolAddress((void**)&hav, g_hav);
    cudaGetSymbolAddress((void**)&hwq, g_hwq);
    cudaGetSymbolAddress((void**)&hwk, g_hwk);
    cudaGetSymbolAddress((void**)&hwv, g_hwv);
    cudaGetSymbolAddress((void**)&hwo, g_hwo);

    static bool attr_set = false;
    if (!attr_set) {
        cudaFuncSetAttribute(gemm_qkv, cudaFuncAttributeMaxDynamicSharedMemorySize, (int)G_SMEM);
        cudaFuncSetAttribute(gemm_out, cudaFuncAttributeMaxDynamicSharedMemorySize, (int)G_SMEM);
        cudaFuncSetAttribute(attn_tc,  cudaFuncAttributeMaxDynamicSharedMemorySize, (int)A_SMEM);
        attr_set = true;
    }

    PPArgs pa;
    const int NG_IN = BSZ * T * E / 16;   // 262144
    const int NG_W  = E * E / 16;         // 65536
    pa.src[0] = queries; pa.dst[0] = haq; pa.ngrp[0] = NG_IN;
    pa.src[1] = keys;    pa.dst[1] = hak; pa.ngrp[1] = NG_IN;
    pa.src[2] = values;  pa.dst[2] = hav; pa.ngrp[2] = NG_IN;
    pa.src[3] = Wq;      pa.dst[3] = hwq; pa.ngrp[3] = NG_W;
    pa.src[4] = Wk;      pa.dst[4] = hwk; pa.ngrp[4] = NG_W;
    pa.src[5] = Wv;      pa.dst[5] = hwv; pa.ngrp[5] = NG_W;
    pa.src[6] = Wo;      pa.dst[6] = hwo; pa.ngrp[6] = NG_W;
    prepass<<<dim3(NG_IN / 256, 1, 7), 256>>>(pa);

    dim3 gq(E / NT, (BSZ * T) / MT, 3);
    gemm_qkv<<<gq, 512, G_SMEM>>>(qp, kp, vp);

    attn_tc<<<dim3(T / 128, BSZ * H), 256, A_SMEM>>>();

    dim3 gg(E / NT, (BSZ * T) / MT);
    gemm_out<<<gg, 512, G_SMEM>>>((float*)d_out);
}

// round 12
// speedup vs baseline: 2.0295x; 1.4302x over previous
#include <cuda_runtime.h>
#include <cuda_fp16.h>
#include <math.h>
#include <stdint.h>

#define BSZ 2
#define T   2048
#define E   1024
#define H   16
#define D   64

// fp16 attention intermediates (pair-interleaved layouts)
__device__ __half g_q[BSZ*T*E];          // Q proj, x0.125, dim-pair-interleaved
__device__ __half g_k[BSZ*T*E];          // K proj, dim-pair-interleaved
__device__ __half g_vT[BSZ*H*D*T];       // V proj transposed, token-interleaved
__device__ __half g_attn[BSZ*T*E];       // attn out, pair-interleaved
// fp16 pair-interleaved GEMM inputs (prepass outputs)
__device__ __half g_haq[BSZ*T*E];
__device__ __half g_hak[BSZ*T*E];
__device__ __half g_hav[BSZ*T*E];
__device__ __half g_hwq[E*E];
__device__ __half g_hwk[E*E];
__device__ __half g_hwv[E*E];
__device__ __half g_hwo[E*E];

// ===========================================================================
// Helpers
// ===========================================================================
__device__ __forceinline__ uint32_t su32(const void* p) {
    return (uint32_t)__cvta_generic_to_shared(p);
}
__device__ __forceinline__ void mma16(float c[4], uint32_t a0, uint32_t a1,
                                      uint32_t a2, uint32_t a3,
                                      uint32_t b0, uint32_t b1) {
    asm("mma.sync.aligned.m16n8k16.row.col.f32.f16.f16.f32 "
        "{%0,%1,%2,%3},{%4,%5,%6,%7},{%8,%9},{%0,%1,%2,%3};"
        : "+f"(c[0]), "+f"(c[1]), "+f"(c[2]), "+f"(c[3])
        : "r"(a0), "r"(a1), "r"(a2), "r"(a3), "r"(b0), "r"(b1));
}
__device__ __forceinline__ void cp16(uint32_t dst, const void* src) {
    asm volatile("cp.async.cg.shared.global [%0], [%1], 16;"
                 :: "r"(dst), "l"(src) : "memory");
}
__device__ __forceinline__ void cp_commit() {
    asm volatile("cp.async.commit_group;" ::: "memory");
}
template <int N>
__device__ __forceinline__ void cp_wait() {
    asm volatile("cp.async.wait_group %0;" :: "n"(N) : "memory");
}
__device__ __forceinline__ uint32_t h2u(__half2 h) { return *(uint32_t*)&h; }

// ===========================================================================
// Prepass: fp32 -> fp16, pair-interleaved within each 16-element k-group:
// out halves = in{0,1, 8,9, 2,3, 10,11, 4,5, 12,13, 6,7, 14,15}
// (input j -> slot 4*((j&7)>>1) + (j&1) + 2*(j>>3))
// ===========================================================================
struct PPArgs {
    const float* src[7];
    __half*      dst[7];
    int          ngrp[7];
};

__global__ __launch_bounds__(256) void prepass(PPArgs a) {
    const int z = blockIdx.z;
    const int i = blockIdx.x * 256 + threadIdx.x;
    if (i >= a.ngrp[z]) return;
    const float4* s = (const float4*)a.src[z] + (size_t)i * 4;
    float4 f0 = s[0], f1 = s[1], f2 = s[2], f3 = s[3];
    uint4 o0, o1;
    o0.x = h2u(__floats2half2_rn(f0.x, f0.y));
    o0.y = h2u(__floats2half2_rn(f2.x, f2.y));
    o0.z = h2u(__floats2half2_rn(f0.z, f0.w));
    o0.w = h2u(__floats2half2_rn(f2.z, f2.w));
    o1.x = h2u(__floats2half2_rn(f1.x, f1.y));
    o1.y = h2u(__floats2half2_rn(f3.x, f3.y));
    o1.z = h2u(__floats2half2_rn(f1.z, f1.w));
    o1.w = h2u(__floats2half2_rn(f3.z, f3.w));
    uint4* d = (uint4*)(a.dst[z] + (size_t)i * 16);
    d[0] = o0; d[1] = o1;
}

// ===========================================================================
// fp16 m16n8k16 GEMM core. CTA 128x256, 512 thr, BK=64 halves, 3-stage.
// mode 0: fp32 out (final output)
// mode 2: fp16 out, x0.125, dim-pair-interleaved        (Q)
// mode 3: fp16 out, dim-pair-interleaved                (K)
// mode 4: fp16 out, TRANSPOSED [b,h,dim,T], token-pair-interleaved (V^T)
// ===========================================================================
#define KDIM 1024
#define MT   128
#define NT   256
#define BKH  64
#define HSTRIDE 80
#define G_WOFFH (MT*HSTRIDE)
#define G_STAGEH ((MT+NT)*HSTRIDE)
#define G_SMEM (3*G_STAGEH*2)

__device__ __forceinline__ void gemm_core(const __half* __restrict__ A,
                                          const __half* __restrict__ W,
                                          float* __restrict__ Cf,
                                          __half* __restrict__ Ch,
                                          int mode, __half* sg) {
    const uint32_t sbase = su32(sg);
    const int tid  = threadIdx.x;
    const int wid  = tid >> 5, lane = tid & 31;
    const int g    = lane >> 2, q = lane & 3;
    const int wr   = wid & 3;
    const int wc   = wid >> 2;
    const int bm   = blockIdx.y * MT;
    const int bn   = blockIdx.x * NT;

    const __half* gA = A + (size_t)bm * KDIM;
    const __half* gW = W + (size_t)bn * KDIM;

    auto cp_stage = [&](int s, int kt) {
        const uint32_t base = sbase + s * (G_STAGEH * 2);
        const int k0 = kt * BKH;
        #pragma unroll
        for (int i = 0; i < 6; i++) {
            int c = tid + i * 512;
            if (c < 1024) {
                int row = c >> 3, ch = c & 7;
                cp16(base + row * (HSTRIDE*2) + ch * 16,
                     gA + (size_t)row * KDIM + k0 + ch * 8);
            } else {
                int cc = c - 1024;
                int row = cc >> 3, ch = cc & 7;
                cp16(base + G_WOFFH*2 + row * (HSTRIDE*2) + ch * 16,
                     gW + (size_t)row * KDIM + k0 + ch * 8);
            }
        }
        cp_commit();
    };

    float acc[2][8][4];
    #pragma unroll
    for (int mi = 0; mi < 2; mi++)
        #pragma unroll
        for (int ni = 0; ni < 8; ni++)
            #pragma unroll
            for (int e = 0; e < 4; e++) acc[mi][ni][e] = 0.f;

    cp_stage(0, 0); cp_stage(1, 1);

    const int NKT = KDIM / BKH;
    int buf = 0;
    for (int kt = 0; kt < NKT; kt++) {
        cp_wait<1>();
        __syncthreads();
        if (kt + 2 < NKT) {
            int nb = buf + 2; if (nb >= 3) nb -= 3;
            cp_stage(nb, kt + 2);
        } else cp_commit();

        const __half* As = sg + buf * G_STAGEH;
        const __half* Ws = As + G_WOFFH;
        const int m0 = wr * 32, n0 = wc * 64;

        #pragma unroll
        for (int kc = 0; kc < 4; kc++) {
            const int hoff = kc * 16 + 4 * q;
            uint2 ra[2], rb[2];
            #pragma unroll
            for (int mi = 0; mi < 2; mi++) {
                ra[mi] = *(const uint2*)&As[(m0 + mi*16 + g) * HSTRIDE + hoff];
                rb[mi] = *(const uint2*)&As[(m0 + mi*16 + g + 8) * HSTRIDE + hoff];
            }
            #pragma unroll
            for (int ni = 0; ni < 8; ni++) {
                uint2 wv = *(const uint2*)&Ws[(n0 + ni*8 + g) * HSTRIDE + hoff];
                mma16(acc[0][ni], ra[0].x, rb[0].x, ra[0].y, rb[0].y, wv.x, wv.y);
                mma16(acc[1][ni], ra[1].x, rb[1].x, ra[1].y, rb[1].y, wv.x, wv.y);
            }
        }
        buf++; if (buf == 3) buf = 0;
    }

    if (mode == 0) {
        #pragma unroll
        for (int mi = 0; mi < 2; mi++) {
            const int r0 = bm + wr * 32 + mi * 16 + g;
            #pragma unroll
            for (int ni = 0; ni < 8; ni++) {
                const int colb = bn + wc * 64 + ni * 8;
                *(float2*)(Cf + (size_t)r0 * E + colb + 2*q) =
                    make_float2(acc[mi][ni][0], acc[mi][ni][1]);
                *(float2*)(Cf + (size_t)(r0+8) * E + colb + 2*q) =
                    make_float2(acc[mi][ni][2], acc[mi][ni][3]);
            }
        }
    } else if (mode == 4) {
        // V^T: token tk -> [b, h, dim, tloc + slot]; slot(g)=4*(g>>1)+(g&1)
        const int slot0 = 4 * (g >> 1) + (g & 1);
        const int slot1 = slot0 + 2;
        #pragma unroll
        for (int mi = 0; mi < 2; mi++) {
            const int tk0 = bm + wr * 32 + mi * 16 + g;
            const int bi  = tk0 >> 11;
            const int tl  = (tk0 & 2047) & ~15;
            #pragma unroll
            for (int ni = 0; ni < 8; ni++) {
                const int c0 = bn + wc * 64 + ni * 8 + 2 * q;
                const int hh = c0 >> 6, d0 = c0 & 63;
                __half* bp = Ch + ((size_t)(bi * H + hh) * D) * T;
                bp[(size_t)d0 * T + tl + slot0]       = __float2half(acc[mi][ni][0]);
                bp[(size_t)(d0 + 1) * T + tl + slot0] = __float2half(acc[mi][ni][1]);
                bp[(size_t)d0 * T + tl + slot1]       = __float2half(acc[mi][ni][2]);
                bp[(size_t)(d0 + 1) * T + tl + slot1] = __float2half(acc[mi][ni][3]);
            }
        }
    } else {
        const float sc = (mode == 2) ? 0.125f : 1.0f;
        #pragma unroll
        for (int mi = 0; mi < 2; mi++) {
            const int r0 = bm + wr * 32 + mi * 16 + g;
            #pragma unroll
            for (int ni = 0; ni < 8; ni++) {
                const int base = bn + wc * 64 + ((ni >> 1) << 4) + 4*q + 2*(ni & 1);
                *(__half2*)(Ch + (size_t)r0 * E + base) =
                    __floats2half2_rn(sc * acc[mi][ni][0], sc * acc[mi][ni][1]);
                *(__half2*)(Ch + (size_t)(r0+8) * E + base) =
                    __floats2half2_rn(sc * acc[mi][ni][2], sc * acc[mi][ni][3]);
            }
        }
    }
}

__global__ __launch_bounds__(512, 1) void gemm_qkv() {
    extern __shared__ __half sg[];
    if (blockIdx.z == 0)      gemm_core(g_haq, g_hwq, nullptr, g_q,  2, sg);
    else if (blockIdx.z == 1) gemm_core(g_hak, g_hwk, nullptr, g_k,  3, sg);
    else                      gemm_core(g_hav, g_hwv, nullptr, g_vT, 4, sg);
}

__global__ __launch_bounds__(512, 1) void gemm_out(float* __restrict__ C) {
    extern __shared__ __half sg[];
    gemm_core(g_attn, g_hwo, C, nullptr, 0, sg);
}

// ===========================================================================
// Causal flash attention, fp16 m16n8k16, fp32 accum.
// 256 thr (8 warps), 128 q-rows/CTA, 64-key tiles, double-buffered cp.async.
// K tile: [token][dim-interleaved 64h] stride 80h; V^T tile: [dim][tok-itl]
// stride 80h. All fragments single LDS.64 (banks 8g+2q: conflict-free).
// P acc layout == fp16 A-frag layout -> ZERO shuffles for P@V.
// Epilogue writes g_attn fp16 pair-interleaved for gemm_out.
// ===========================================================================
#define AKH (64*80)                       // halves per K buffer
#define AKB (AKH*2)                       // bytes (10240)
#define A_SMEM (4*AKB)                    // K0,K1,V0,V1 = 40960 B

__global__ __launch_bounds__(256, 2) void attn_tc() {
    extern __shared__ __half sh[];
    const uint32_t sbase = su32(sh);

    const int tid = threadIdx.x;
    const int w = tid >> 5, lane = tid & 31;
    const int g = lane >> 2, q = lane & 3;
    const int b = blockIdx.y / H, h = blockIdx.y % H;
    const int qt = gridDim.x - 1 - blockIdx.x;
    const int qbase = qt * 128;
    const int jmax = 2 * qt + 1;

    const __half* Kg  = g_k + (size_t)(b * T) * E + h * D;
    const __half* Vtg = g_vT + (size_t)((b * H + h) * D) * T;

    // Q a-frags (fp16, interleaved, 0.125 pre-folded): 8 LDG.64
    const __half* Q0 = g_q + (size_t)(b * T + qbase + w * 16 + g) * E + h * D;
    uint32_t qa[4][4];
    #pragma unroll
    for (int kc = 0; kc < 4; kc++) {
        uint2 x0 = *(const uint2*)&Q0[kc * 16 + 4 * q];
        uint2 x1 = *(const uint2*)&Q0[(size_t)8 * E + kc * 16 + 4 * q];
        qa[kc][0] = x0.x; qa[kc][1] = x1.x; qa[kc][2] = x0.y; qa[kc][3] = x1.y;
    }

    auto stage = [&](int j) {
        const int buf = j & 1;
        const int kbase = j * 64;
        const uint32_t kdst = sbase + buf * AKB;
        const uint32_t vdst = sbase + (2 + buf) * AKB;
        #pragma unroll
        for (int t = 0; t < 4; t++) {
            int c = tid + t * 256;               // 0..1023
            if (c < 512) {                        // K: 64 token-rows x 8 chunks
                int row = c >> 3, ch = c & 7;
                cp16(kdst + row * 160 + ch * 16,
                     Kg + (size_t)(kbase + row) * E + ch * 8);
            } else {                              // V^T: 64 dim-rows x 8 chunks
                int cc = c - 512;
                int row = cc >> 3, ch = cc & 7;
                cp16(vdst + row * 160 + ch * 16,
                     Vtg + (size_t)row * T + kbase + ch * 8);
            }
        }
        cp_commit();
    };

    float oacc[8][4];
    #pragma unroll
    for (int nt = 0; nt < 8; nt++)
        #pragma unroll
        for (int e = 0; e < 4; e++) oacc[nt][e] = 0.f;

    float m0 = -INFINITY, m1 = -INFINITY, l0 = 0.f, l1 = 0.f;
    const int r0g = qbase + w * 16 + g, r1g = r0g + 8;
    const int wmaxrow = qbase + w * 16 + 15;

    stage(0);

    for (int j = 0; j <= jmax; j++) {
        __syncthreads();
        if (j < jmax) stage(j + 1);
        else          cp_commit();
        cp_wait<1>();
        __syncthreads();

        const int kbase = j * 64;
        if (kbase > wmaxrow) continue;

        const __half* Ks = sh + (j & 1) * AKH;
        const __half* Vs = sh + (2 + (j & 1)) * AKH;

        // S = Q @ K^T : 32 mma16, 32 LDS.64
        float sacc[8][4];
        #pragma unroll
        for (int nt = 0; nt < 8; nt++) {
            #pragma unroll
            for (int e = 0; e < 4; e++) sacc[nt][e] = 0.f;
            const __half* kp = Ks + (nt * 8 + g) * 80 + 4 * q;
            #pragma unroll
            for (int kc = 0; kc < 4; kc++) {
                uint2 kb = *(const uint2*)&kp[kc * 16];
                mma16(sacc[nt], qa[kc][0], qa[kc][1], qa[kc][2], qa[kc][3],
                      kb.x, kb.y);
            }
        }

        if (kbase + 63 > r0g) {
            #pragma unroll
            for (int nt = 0; nt < 8; nt++) {
                #pragma unroll
                for (int e = 0; e < 2; e++) {
                    int colg = kbase + nt * 8 + 2 * q + e;
                    if (colg > r0g) sacc[nt][e]     = -INFINITY;
                    if (colg > r1g) sacc[nt][2 + e] = -INFINITY;
                }
            }
        }

        // Online softmax
        float mx0 = -INFINITY, mx1 = -INFINITY;
        #pragma unroll
        for (int nt = 0; nt < 8; nt++) {
            mx0 = fmaxf(mx0, fmaxf(sacc[nt][0], sacc[nt][1]));
            mx1 = fmaxf(mx1, fmaxf(sacc[nt][2], sacc[nt][3]));
        }
        mx0 = fmaxf(mx0, __shfl_xor_sync(0xffffffffu, mx0, 1));
        mx0 = fmaxf(mx0, __shfl_xor_sync(0xffffffffu, mx0, 2));
        mx1 = fmaxf(mx1, __shfl_xor_sync(0xffffffffu, mx1, 1));
        mx1 = fmaxf(mx1, __shfl_xor_sync(0xffffffffu, mx1, 2));
        float mn0 = fmaxf(m0, mx0), mn1 = fmaxf(m1, mx1);
        float sc0 = __expf(m0 - mn0), sc1 = __expf(m1 - mn1);

        float s0 = 0.f, s1 = 0.f;
        uint32_t ph[8][2];                    // P packed: [nt] {rows g | g+8}
        #pragma unroll
        for (int nt = 0; nt < 8; nt++) {
            float p0 = __expf(sacc[nt][0] - mn0);
            float p1 = __expf(sacc[nt][1] - mn0);
            float p2 = __expf(sacc[nt][2] - mn1);
            float p3 = __expf(sacc[nt][3] - mn1);
            s0 += p0 + p1; s1 += p2 + p3;
            ph[nt][0] = h2u(__floats2half2_rn(p0, p1));
            ph[nt][1] = h2u(__floats2half2_rn(p2, p3));
        }
        s0 += __shfl_xor_sync(0xffffffffu, s0, 1);
        s0 += __shfl_xor_sync(0xffffffffu, s0, 2);
        s1 += __shfl_xor_sync(0xffffffffu, s1, 1);
        s1 += __shfl_xor_sync(0xffffffffu, s1, 2);
        l0 = l0 * sc0 + s0; l1 = l1 * sc1 + s1;
        m0 = mn0; m1 = mn1;
        #pragma unroll
        for (int nt = 0; nt < 8; nt++) {
            oacc[nt][0] *= sc0; oacc[nt][1] *= sc0;
            oacc[nt][2] *= sc1; oacc[nt][3] *= sc1;
        }

        // O += P @ V : P acc layout == A-frag layout (no shuffles).
        // a(kc) = {ph[2kc][0], ph[2kc][1], ph[2kc+1][0], ph[2kc+1][1]}
        #pragma unroll
        for (int nt = 0; nt < 8; nt++) {
            const __half* vp = Vs + (nt * 8 + g) * 80 + 4 * q;
            #pragma unroll
            for (int kc = 0; kc < 4; kc++) {
                uint2 vb = *(const uint2*)&vp[kc * 16];
                mma16(oacc[nt], ph[2*kc][0], ph[2*kc][1],
                      ph[2*kc+1][0], ph[2*kc+1][1], vb.x, vb.y);
            }
        }
    }

    // Epilogue: fp16, pair-interleaved for gemm_out
    const float inv0 = 1.f / l0, inv1 = 1.f / l1;
    __half* O0 = g_attn + ((size_t)(b * T + r0g)) * E + h * D;
    __half* O1 = g_attn + ((size_t)(b * T + r1g)) * E + h * D;
    #pragma unroll
    for (int nt = 0; nt < 8; nt++) {
        int idx = ((nt >> 1) << 4) + 4 * q + 2 * (nt & 1);
        *(__half2*)(O0 + idx) = __floats2half2_rn(oacc[nt][0] * inv0,
                                                  oacc[nt][1] * inv0);
        *(__half2*)(O1 + idx) = __floats2half2_rn(oacc[nt][2] * inv1,
                                                  oacc[nt][3] * inv1);
    }
}

// ===========================================================================
// Inputs: queries, keys, values, mask(unused), Wq, Wk, Wv, Wo
// ===========================================================================
extern "C" void kernel_launch(void* const* d_in, const int* in_sizes, int n_in,
                              void* d_out, int out_size) {
    const float* queries = (const float*)d_in[0];
    const float* keys    = (const float*)d_in[1];
    const float* values  = (const float*)d_in[2];
    const float* Wq      = (const float*)d_in[4];
    const float* Wk      = (const float*)d_in[5];
    const float* Wv      = (const float*)d_in[6];
    const float* Wo      = (const float*)d_in[7];

    __half *haq, *hak, *hav, *hwq, *hwk, *hwv, *hwo;
    cudaGetSymbolAddress((void**)&haq, g_haq);
    cudaGetSymbolAddress((void**)&hak, g_hak);
    cudaGetSymbolAddress((void**)&hav, g_hav);
    cudaGetSymbolAddress((void**)&hwq, g_hwq);
    cudaGetSymbolAddress((void**)&hwk, g_hwk);
    cudaGetSymbolAddress((void**)&hwv, g_hwv);
    cudaGetSymbolAddress((void**)&hwo, g_hwo);

    static bool attr_set = false;
    if (!attr_set) {
        cudaFuncSetAttribute(gemm_qkv, cudaFuncAttributeMaxDynamicSharedMemorySize, (int)G_SMEM);
        cudaFuncSetAttribute(gemm_out, cudaFuncAttributeMaxDynamicSharedMemorySize, (int)G_SMEM);
        cudaFuncSetAttribute(attn_tc,  cudaFuncAttributeMaxDynamicSharedMemorySize, (int)A_SMEM);
        attr_set = true;
    }

    PPArgs pa;
    const int NG_IN = BSZ * T * E / 16;
    const int NG_W  = E * E / 16;
    pa.src[0] = queries; pa.dst[0] = haq; pa.ngrp[0] = NG_IN;
    pa.src[1] = keys;    pa.dst[1] = hak; pa.ngrp[1] = NG_IN;
    pa.src[2] = values;  pa.dst[2] = hav; pa.ngrp[2] = NG_IN;
    pa.src[3] = Wq;      pa.dst[3] = hwq; pa.ngrp[3] = NG_W;
    pa.src[4] = Wk;      pa.dst[4] = hwk; pa.ngrp[4] = NG_W;
    pa.src[5] = Wv;      pa.dst[5] = hwv; pa.ngrp[5] = NG_W;
    pa.src[6] = Wo;      pa.dst[6] = hwo; pa.ngrp[6] = NG_W;
    prepass<<<dim3(NG_IN / 256, 1, 7), 256>>>(pa);

    dim3 gq(E / NT, (BSZ * T) / MT, 3);
    gemm_qkv<<<gq, 512, G_SMEM>>>();

    attn_tc<<<dim3(T / 128, BSZ * H), 256, A_SMEM>>>();

    dim3 gg(E / NT, (BSZ * T) / MT);
    gemm_out<<<gg, 512, G_SMEM>>>((float*)d_out);
}

// round 13
// speedup vs baseline: 2.0480x; 1.0091x over previous
#include <cuda_runtime.h>
#include <cuda_fp16.h>
#include <math.h>
#include <stdint.h>

#define BSZ 2
#define T   2048
#define E   1024
#define H   16
#define D   64

// fp16 attention intermediates (pair-interleaved layouts)
__device__ __half g_q[BSZ*T*E];          // Q proj, x0.125, dim-pair-interleaved
__device__ __half g_k[BSZ*T*E];          // K proj, dim-pair-interleaved
__device__ __half g_vT[BSZ*H*D*T];       // V proj transposed, token-interleaved
__device__ __half g_attn[BSZ*T*E];       // attn out, pair-interleaved
// fp16 pair-interleaved GEMM inputs (prepass outputs)
__device__ __half g_haq[BSZ*T*E];
__device__ __half g_hak[BSZ*T*E];
__device__ __half g_hav[BSZ*T*E];
__device__ __half g_hwq[E*E];
__device__ __half g_hwk[E*E];
__device__ __half g_hwv[E*E];
__device__ __half g_hwo[E*E];

// ===========================================================================
// Helpers
// ===========================================================================
__device__ __forceinline__ uint32_t su32(const void* p) {
    return (uint32_t)__cvta_generic_to_shared(p);
}
__device__ __forceinline__ void mma16(float c[4], uint32_t a0, uint32_t a1,
                                      uint32_t a2, uint32_t a3,
                                      uint32_t b0, uint32_t b1) {
    asm("mma.sync.aligned.m16n8k16.row.col.f32.f16.f16.f32 "
        "{%0,%1,%2,%3},{%4,%5,%6,%7},{%8,%9},{%0,%1,%2,%3};"
        : "+f"(c[0]), "+f"(c[1]), "+f"(c[2]), "+f"(c[3])
        : "r"(a0), "r"(a1), "r"(a2), "r"(a3), "r"(b0), "r"(b1));
}
__device__ __forceinline__ void cp16(uint32_t dst, const void* src) {
    asm volatile("cp.async.cg.shared.global [%0], [%1], 16;"
                 :: "r"(dst), "l"(src) : "memory");
}
__device__ __forceinline__ void cp_commit() {
    asm volatile("cp.async.commit_group;" ::: "memory");
}
template <int N>
__device__ __forceinline__ void cp_wait() {
    asm volatile("cp.async.wait_group %0;" :: "n"(N) : "memory");
}
__device__ __forceinline__ uint32_t h2u(__half2 h) { return *(uint32_t*)&h; }

// ===========================================================================
// Prepass: fp32 -> fp16, pair-interleaved within each 16-element k-group:
// out halves = in{0,1, 8,9, 2,3, 10,11, 4,5, 12,13, 6,7, 14,15}
// ===========================================================================
struct PPArgs {
    const float* src[7];
    __half*      dst[7];
    int          ngrp[7];
};

__global__ __launch_bounds__(256) void prepass(PPArgs a) {
    const int z = blockIdx.z;
    const int i = blockIdx.x * 256 + threadIdx.x;
    if (i >= a.ngrp[z]) return;
    const float4* s = (const float4*)a.src[z] + (size_t)i * 4;
    float4 f0 = s[0], f1 = s[1], f2 = s[2], f3 = s[3];
    uint4 o0, o1;
    o0.x = h2u(__floats2half2_rn(f0.x, f0.y));
    o0.y = h2u(__floats2half2_rn(f2.x, f2.y));
    o0.z = h2u(__floats2half2_rn(f0.z, f0.w));
    o0.w = h2u(__floats2half2_rn(f2.z, f2.w));
    o1.x = h2u(__floats2half2_rn(f1.x, f1.y));
    o1.y = h2u(__floats2half2_rn(f3.x, f3.y));
    o1.z = h2u(__floats2half2_rn(f1.z, f1.w));
    o1.w = h2u(__floats2half2_rn(f3.z, f3.w));
    uint4* d = (uint4*)(a.dst[z] + (size_t)i * 16);
    d[0] = o0; d[1] = o1;
}

// ===========================================================================
// fp16 m16n8k16 GEMM core. CTA 128x128, 256 thr (8 warps, warp 32x64),
// BK=64 halves, 2-stage double buffer -> 80 KB smem -> 2 CTAs/SM.
// mode 0: fp32 out (final output)
// mode 2: fp16 out, x0.125, dim-pair-interleaved        (Q)
// mode 3: fp16 out, dim-pair-interleaved                (K)
// mode 4: fp16 out, TRANSPOSED [b,h,dim,T], token-pair-interleaved (V^T)
// ===========================================================================
#define KDIM 1024
#define MT   128
#define NT   128
#define BKH  64
#define HSTRIDE 80
#define G_WOFFH (MT*HSTRIDE)
#define G_STAGEH ((MT+NT)*HSTRIDE)           // 20480 halves = 40960 B
#define G_SMEM (2*G_STAGEH*2)                // 81920 B

__device__ __forceinline__ void gemm_core(const __half* __restrict__ A,
                                          const __half* __restrict__ W,
                                          float* __restrict__ Cf,
                                          __half* __restrict__ Ch,
                                          int mode, __half* sg) {
    const uint32_t sbase = su32(sg);
    const int tid  = threadIdx.x;
    const int wid  = tid >> 5, lane = tid & 31;
    const int g    = lane >> 2, q = lane & 3;
    const int wr   = wid & 3;          // 4 m-groups x 32 rows
    const int wc   = wid >> 2;         // 2 n-groups x 64 cols
    const int bm   = blockIdx.y * MT;
    const int bn   = blockIdx.x * NT;

    const __half* gA = A + (size_t)bm * KDIM;
    const __half* gW = W + (size_t)bn * KDIM;

    auto cp_stage = [&](int s, int kt) {
        const uint32_t base = sbase + s * (G_STAGEH * 2);
        const int k0 = kt * BKH;
        #pragma unroll
        for (int i = 0; i < 8; i++) {
            int c = tid + i * 256;                   // 0..2047
            if (c < 1024) {                           // A: 128 rows x 8 chunks
                int row = c >> 3, ch = c & 7;
                cp16(base + row * (HSTRIDE*2) + ch * 16,
                     gA + (size_t)row * KDIM + k0 + ch * 8);
            } else {                                  // W: 128 rows x 8 chunks
                int cc = c - 1024;
                int row = cc >> 3, ch = cc & 7;
                cp16(base + G_WOFFH*2 + row * (HSTRIDE*2) + ch * 16,
                     gW + (size_t)row * KDIM + k0 + ch * 8);
            }
        }
        cp_commit();
    };

    float acc[2][8][4];
    #pragma unroll
    for (int mi = 0; mi < 2; mi++)
        #pragma unroll
        for (int ni = 0; ni < 8; ni++)
            #pragma unroll
            for (int e = 0; e < 4; e++) acc[mi][ni][e] = 0.f;

    cp_stage(0, 0);

    const int NKT = KDIM / BKH;   // 16
    for (int kt = 0; kt < NKT; kt++) {
        __syncthreads();                        // prev compute done: buffer free
        if (kt + 1 < NKT) cp_stage((kt + 1) & 1, kt + 1);
        else              cp_commit();
        cp_wait<1>();                           // stage kt complete
        __syncthreads();

        const __half* As = sg + (kt & 1) * G_STAGEH;
        const __half* Ws = As + G_WOFFH;
        const int m0 = wr * 32, n0 = wc * 64;

        #pragma unroll
        for (int kc = 0; kc < 4; kc++) {
            const int hoff = kc * 16 + 4 * q;
            uint2 ra[2], rb[2];
            #pragma unroll
            for (int mi = 0; mi < 2; mi++) {
                ra[mi] = *(const uint2*)&As[(m0 + mi*16 + g) * HSTRIDE + hoff];
                rb[mi] = *(const uint2*)&As[(m0 + mi*16 + g + 8) * HSTRIDE + hoff];
            }
            #pragma unroll
            for (int ni = 0; ni < 8; ni++) {
                uint2 wv = *(const uint2*)&Ws[(n0 + ni*8 + g) * HSTRIDE + hoff];
                mma16(acc[0][ni], ra[0].x, rb[0].x, ra[0].y, rb[0].y, wv.x, wv.y);
                mma16(acc[1][ni], ra[1].x, rb[1].x, ra[1].y, rb[1].y, wv.x, wv.y);
            }
        }
    }

    if (mode == 0) {
        #pragma unroll
        for (int mi = 0; mi < 2; mi++) {
            const int r0 = bm + wr * 32 + mi * 16 + g;
            #pragma unroll
            for (int ni = 0; ni < 8; ni++) {
                const int colb = bn + wc * 64 + ni * 8;
                *(float2*)(Cf + (size_t)r0 * E + colb + 2*q) =
                    make_float2(acc[mi][ni][0], acc[mi][ni][1]);
                *(float2*)(Cf + (size_t)(r0+8) * E + colb + 2*q) =
                    make_float2(acc[mi][ni][2], acc[mi][ni][3]);
            }
        }
    } else if (mode == 4) {
        // V^T: token tk -> [b, h, dim, tloc + slot]; slot(g)=4*(g>>1)+(g&1)
        const int slot0 = 4 * (g >> 1) + (g & 1);
        const int slot1 = slot0 + 2;
        #pragma unroll
        for (int mi = 0; mi < 2; mi++) {
            const int tk0 = bm + wr * 32 + mi * 16 + g;
            const int bi  = tk0 >> 11;
            const int tl  = (tk0 & 2047) & ~15;
            #pragma unroll
            for (int ni = 0; ni < 8; ni++) {
                const int c0 = bn + wc * 64 + ni * 8 + 2 * q;
                const int hh = c0 >> 6, d0 = c0 & 63;
                __half* bp = Ch + ((size_t)(bi * H + hh) * D) * T;
                bp[(size_t)d0 * T + tl + slot0]       = __float2half(acc[mi][ni][0]);
                bp[(size_t)(d0 + 1) * T + tl + slot0] = __float2half(acc[mi][ni][1]);
                bp[(size_t)d0 * T + tl + slot1]       = __float2half(acc[mi][ni][2]);
                bp[(size_t)(d0 + 1) * T + tl + slot1] = __float2half(acc[mi][ni][3]);
            }
        }
    } else {
        const float sc = (mode == 2) ? 0.125f : 1.0f;
        #pragma unroll
        for (int mi = 0; mi < 2; mi++) {
            const int r0 = bm + wr * 32 + mi * 16 + g;
            #pragma unroll
            for (int ni = 0; ni < 8; ni++) {
                const int base = bn + wc * 64 + ((ni >> 1) << 4) + 4*q + 2*(ni & 1);
                *(__half2*)(Ch + (size_t)r0 * E + base) =
                    __floats2half2_rn(sc * acc[mi][ni][0], sc * acc[mi][ni][1]);
                *(__half2*)(Ch + (size_t)(r0+8) * E + base) =
                    __floats2half2_rn(sc * acc[mi][ni][2], sc * acc[mi][ni][3]);
            }
        }
    }
}

__global__ __launch_bounds__(256, 2) void gemm_qkv() {
    extern __shared__ __half sg[];
    if (blockIdx.z == 0)      gemm_core(g_haq, g_hwq, nullptr, g_q,  2, sg);
    else if (blockIdx.z == 1) gemm_core(g_hak, g_hwk, nullptr, g_k,  3, sg);
    else                      gemm_core(g_hav, g_hwv, nullptr, g_vT, 4, sg);
}

__global__ __launch_bounds__(256, 2) void gemm_out(float* __restrict__ C) {
    extern __shared__ __half sg[];
    gemm_core(g_attn, g_hwo, C, nullptr, 0, sg);
}

// ===========================================================================
// Causal flash attention, fp16 m16n8k16, fp32 accum (unchanged from R12).
// ===========================================================================
#define AKH (64*80)
#define AKB (AKH*2)
#define A_SMEM (4*AKB)                    // 40960 B

__global__ __launch_bounds__(256, 2) void attn_tc() {
    extern __shared__ __half sh[];
    const uint32_t sbase = su32(sh);

    const int tid = threadIdx.x;
    const int w = tid >> 5, lane = tid & 31;
    const int g = lane >> 2, q = lane & 3;
    const int b = blockIdx.y / H, h = blockIdx.y % H;
    const int qt = gridDim.x - 1 - blockIdx.x;
    const int qbase = qt * 128;
    const int jmax = 2 * qt + 1;

    const __half* Kg  = g_k + (size_t)(b * T) * E + h * D;
    const __half* Vtg = g_vT + (size_t)((b * H + h) * D) * T;

    const __half* Q0 = g_q + (size_t)(b * T + qbase + w * 16 + g) * E + h * D;
    uint32_t qa[4][4];
    #pragma unroll
    for (int kc = 0; kc < 4; kc++) {
        uint2 x0 = *(const uint2*)&Q0[kc * 16 + 4 * q];
        uint2 x1 = *(const uint2*)&Q0[(size_t)8 * E + kc * 16 + 4 * q];
        qa[kc][0] = x0.x; qa[kc][1] = x1.x; qa[kc][2] = x0.y; qa[kc][3] = x1.y;
    }

    auto stage = [&](int j) {
        const int buf = j & 1;
        const int kbase = j * 64;
        const uint32_t kdst = sbase + buf * AKB;
        const uint32_t vdst = sbase + (2 + buf) * AKB;
        #pragma unroll
        for (int t = 0; t < 4; t++) {
            int c = tid + t * 256;
            if (c < 512) {
                int row = c >> 3, ch = c & 7;
                cp16(kdst + row * 160 + ch * 16,
                     Kg + (size_t)(kbase + row) * E + ch * 8);
            } else {
                int cc = c - 512;
                int row = cc >> 3, ch = cc & 7;
                cp16(vdst + row * 160 + ch * 16,
                     Vtg + (size_t)row * T + kbase + ch * 8);
            }
        }
        cp_commit();
    };

    float oacc[8][4];
    #pragma unroll
    for (int nt = 0; nt < 8; nt++)
        #pragma unroll
        for (int e = 0; e < 4; e++) oacc[nt][e] = 0.f;

    float m0 = -INFINITY, m1 = -INFINITY, l0 = 0.f, l1 = 0.f;
    const int r0g = qbase + w * 16 + g, r1g = r0g + 8;
    const int wmaxrow = qbase + w * 16 + 15;

    stage(0);

    for (int j = 0; j <= jmax; j++) {
        __syncthreads();
        if (j < jmax) stage(j + 1);
        else          cp_commit();
        cp_wait<1>();
        __syncthreads();

        const int kbase = j * 64;
        if (kbase > wmaxrow) continue;

        const __half* Ks = sh + (j & 1) * AKH;
        const __half* Vs = sh + (2 + (j & 1)) * AKH;

        float sacc[8][4];
        #pragma unroll
        for (int nt = 0; nt < 8; nt++) {
            #pragma unroll
            for (int e = 0; e < 4; e++) sacc[nt][e] = 0.f;
            const __half* kp = Ks + (nt * 8 + g) * 80 + 4 * q;
            #pragma unroll
            for (int kc = 0; kc < 4; kc++) {
                uint2 kb = *(const uint2*)&kp[kc * 16];
                mma16(sacc[nt], qa[kc][0], qa[kc][1], qa[kc][2], qa[kc][3],
                      kb.x, kb.y);
            }
        }

        if (kbase + 63 > r0g) {
            #pragma unroll
            for (int nt = 0; nt < 8; nt++) {
                #pragma unroll
                for (int e = 0; e < 2; e++) {
                    int colg = kbase + nt * 8 + 2 * q + e;
                    if (colg > r0g) sacc[nt][e]     = -INFINITY;
                    if (colg > r1g) sacc[nt][2 + e] = -INFINITY;
                }
            }
        }

        float mx0 = -INFINITY, mx1 = -INFINITY;
        #pragma unroll
        for (int nt = 0; nt < 8; nt++) {
            mx0 = fmaxf(mx0, fmaxf(sacc[nt][0], sacc[nt][1]));
            mx1 = fmaxf(mx1, fmaxf(sacc[nt][2], sacc[nt][3]));
        }
        mx0 = fmaxf(mx0, __shfl_xor_sync(0xffffffffu, mx0, 1));
        mx0 = fmaxf(mx0, __shfl_xor_sync(0xffffffffu, mx0, 2));
        mx1 = fmaxf(mx1, __shfl_xor_sync(0xffffffffu, mx1, 1));
        mx1 = fmaxf(mx1, __shfl_xor_sync(0xffffffffu, mx1, 2));
        float mn0 = fmaxf(m0, mx0), mn1 = fmaxf(m1, mx1);
        float sc0 = __expf(m0 - mn0), sc1 = __expf(m1 - mn1);

        float s0 = 0.f, s1 = 0.f;
        uint32_t ph[8][2];
        #pragma unroll
        for (int nt = 0; nt < 8; nt++) {
            float p0 = __expf(sacc[nt][0] - mn0);
            float p1 = __expf(sacc[nt][1] - mn0);
            float p2 = __expf(sacc[nt][2] - mn1);
            float p3 = __expf(sacc[nt][3] - mn1);
            s0 += p0 + p1; s1 += p2 + p3;
            ph[nt][0] = h2u(__floats2half2_rn(p0, p1));
            ph[nt][1] = h2u(__floats2half2_rn(p2, p3));
        }
        s0 += __shfl_xor_sync(0xffffffffu, s0, 1);
        s0 += __shfl_xor_sync(0xffffffffu, s0, 2);
        s1 += __shfl_xor_sync(0xffffffffu, s1, 1);
        s1 += __shfl_xor_sync(0xffffffffu, s1, 2);
        l0 = l0 * sc0 + s0; l1 = l1 * sc1 + s1;
        m0 = mn0; m1 = mn1;
        #pragma unroll
        for (int nt = 0; nt < 8; nt++) {
            oacc[nt][0] *= sc0; oacc[nt][1] *= sc0;
            oacc[nt][2] *= sc1; oacc[nt][3] *= sc1;
        }

        #pragma unroll
        for (int nt = 0; nt < 8; nt++) {
            const __half* vp = Vs + (nt * 8 + g) * 80 + 4 * q;
            #pragma unroll
            for (int kc = 0; kc < 4; kc++) {
                uint2 vb = *(const uint2*)&vp[kc * 16];
                mma16(oacc[nt], ph[2*kc][0], ph[2*kc][1],
                      ph[2*kc+1][0], ph[2*kc+1][1], vb.x, vb.y);
            }
        }
    }

    const float inv0 = 1.f / l0, inv1 = 1.f / l1;
    __half* O0 = g_attn + ((size_t)(b * T + r0g)) * E + h * D;
    __half* O1 = g_attn + ((size_t)(b * T + r1g)) * E + h * D;
    #pragma unroll
    for (int nt = 0; nt < 8; nt++) {
        int idx = ((nt >> 1) << 4) + 4 * q + 2 * (nt & 1);
        *(__half2*)(O0 + idx) = __floats2half2_rn(oacc[nt][0] * inv0,
                                                  oacc[nt][1] * inv0);
        *(__half2*)(O1 + idx) = __floats2half2_rn(oacc[nt][2] * inv1,
                                                  oacc[nt][3] * inv1);
    }
}

// ===========================================================================
// Inputs: queries, keys, values, mask(unused), Wq, Wk, Wv, Wo
// ===========================================================================
extern "C" void kernel_launch(void* const* d_in, const int* in_sizes, int n_in,
                              void* d_out, int out_size) {
    const float* queries = (const float*)d_in[0];
    const float* keys    = (const float*)d_in[1];
    const float* values  = (const float*)d_in[2];
    const float* Wq      = (const float*)d_in[4];
    const float* Wk      = (const float*)d_in[5];
    const float* Wv      = (const float*)d_in[6];
    const float* Wo      = (const float*)d_in[7];

    __half *haq, *hak, *hav, *hwq, *hwk, *hwv, *hwo;
    cudaGetSymbolAddress((void**)&haq, g_haq);
    cudaGetSymbolAddress((void**)&hak, g_hak);
    cudaGetSymbolAddress((void**)&hav, g_hav);
    cudaGetSymbolAddress((void**)&hwq, g_hwq);
    cudaGetSymbolAddress((void**)&hwk, g_hwk);
    cudaGetSymbolAddress((void**)&hwv, g_hwv);
    cudaGetSymbolAddress((void**)&hwo, g_hwo);

    static bool attr_set = false;
    if (!attr_set) {
        cudaFuncSetAttribute(gemm_qkv, cudaFuncAttributeMaxDynamicSharedMemorySize, (int)G_SMEM);
        cudaFuncSetAttribute(gemm_out, cudaFuncAttributeMaxDynamicSharedMemorySize, (int)G_SMEM);
        cudaFuncSetAttribute(attn_tc,  cudaFuncAttributeMaxDynamicSharedMemorySize, (int)A_SMEM);
        attr_set = true;
    }

    PPArgs pa;
    const int NG_IN = BSZ * T * E / 16;
    const int NG_W  = E * E / 16;
    pa.src[0] = queries; pa.dst[0] = haq; pa.ngrp[0] = NG_IN;
    pa.src[1] = keys;    pa.dst[1] = hak; pa.ngrp[1] = NG_IN;
    pa.src[2] = values;  pa.dst[2] = hav; pa.ngrp[2] = NG_IN;
    pa.src[3] = Wq;      pa.dst[3] = hwq; pa.ngrp[3] = NG_W;
    pa.src[4] = Wk;      pa.dst[4] = hwk; pa.ngrp[4] = NG_W;
    pa.src[5] = Wv;      pa.dst[5] = hwv; pa.ngrp[5] = NG_W;
    pa.src[6] = Wo;      pa.dst[6] = hwo; pa.ngrp[6] = NG_W;
    prepass<<<dim3(NG_IN / 256, 1, 7), 256>>>(pa);

    dim3 gq(E / NT, (BSZ * T) / MT, 3);     // (8, 32, 3) = 768 CTAs
    gemm_qkv<<<gq, 256, G_SMEM>>>();

    attn_tc<<<dim3(T / 128, BSZ * H), 256, A_SMEM>>>();

    dim3 gg(E / NT, (BSZ * T) / MT);        // (8, 32) = 256 CTAs
    gemm_out<<<gg, 256, G_SMEM>>>((float*)d_out);
}

// round 14
// speedup vs baseline: 2.2917x; 1.1190x over previous
#include <cuda_runtime.h>
#include <cuda_fp16.h>
#include <math.h>
#include <stdint.h>

#define BSZ 2
#define T   2048
#define E   1024
#define H   16
#define D   64

// fp16 attention intermediates
__device__ __half g_q[BSZ*T*E];          // Q proj, x0.125, dim-pair-interleaved
__device__ __half g_k[BSZ*T*E];          // K proj, dim-pair-interleaved
__device__ __half g_vT[BSZ*H*D*T];       // V proj transposed, token-interleaved
__device__ __half g_attn[BSZ*T*E];       // attn out, PLAIN row-major fp16
// fp16 PLAIN row-major GEMM inputs (prepass outputs)
__device__ __half g_haq[BSZ*T*E];
__device__ __half g_hak[BSZ*T*E];
__device__ __half g_hav[BSZ*T*E];
__device__ __half g_hwq[E*E];
__device__ __half g_hwk[E*E];
__device__ __half g_hwv[E*E];
__device__ __half g_hwo[E*E];

// ===========================================================================
// Helpers
// ===========================================================================
__device__ __forceinline__ uint32_t su32(const void* p) {
    return (uint32_t)__cvta_generic_to_shared(p);
}
__device__ __forceinline__ void mma16(float c[4], uint32_t a0, uint32_t a1,
                                      uint32_t a2, uint32_t a3,
                                      uint32_t b0, uint32_t b1) {
    asm("mma.sync.aligned.m16n8k16.row.col.f32.f16.f16.f32 "
        "{%0,%1,%2,%3},{%4,%5,%6,%7},{%8,%9},{%0,%1,%2,%3};"
        : "+f"(c[0]), "+f"(c[1]), "+f"(c[2]), "+f"(c[3])
        : "r"(a0), "r"(a1), "r"(a2), "r"(a3), "r"(b0), "r"(b1));
}
__device__ __forceinline__ void ldsm4(uint32_t& r0, uint32_t& r1,
                                      uint32_t& r2, uint32_t& r3, uint32_t addr) {
    asm volatile("ldmatrix.sync.aligned.m8n8.x4.shared.b16 {%0,%1,%2,%3}, [%4];"
                 : "=r"(r0), "=r"(r1), "=r"(r2), "=r"(r3) : "r"(addr));
}
__device__ __forceinline__ void cp16(uint32_t dst, const void* src) {
    asm volatile("cp.async.cg.shared.global [%0], [%1], 16;"
                 :: "r"(dst), "l"(src) : "memory");
}
__device__ __forceinline__ void cp_commit() {
    asm volatile("cp.async.commit_group;" ::: "memory");
}
template <int N>
__device__ __forceinline__ void cp_wait() {
    asm volatile("cp.async.wait_group %0;" :: "n"(N) : "memory");
}
__device__ __forceinline__ uint32_t h2u(__half2 h) { return *(uint32_t*)&h; }

// ===========================================================================
// Prepass: plain fp32 -> fp16 convert (8 elems / thread)
// ===========================================================================
struct PPArgs {
    const float* src[7];
    __half*      dst[7];
    int          ngrp[7];     // number of 8-float groups
};

__global__ __launch_bounds__(256) void prepass(PPArgs a) {
    const int z = blockIdx.z;
    const int i = blockIdx.x * 256 + threadIdx.x;
    if (i >= a.ngrp[z]) return;
    const float4* s = (const float4*)a.src[z] + (size_t)i * 2;
    float4 f0 = s[0], f1 = s[1];
    uint4 o;
    o.x = h2u(__floats2half2_rn(f0.x, f0.y));
    o.y = h2u(__floats2half2_rn(f0.z, f0.w));
    o.z = h2u(__floats2half2_rn(f1.x, f1.y));
    o.w = h2u(__floats2half2_rn(f1.z, f1.w));
    *(uint4*)(a.dst[z] + (size_t)i * 8) = o;
}

// ===========================================================================
// fp16 m16n8k16 GEMM, ldmatrix.x4 operand loads.
// CTA 256x128, 256 thr (8 warps), warp tile 64x64, BK=64 halves, 3-stage.
// Smem: plain row-major 64-half (128 B) rows, chunk-XOR swizzle
// phys_chunk = ch ^ (row&7)  -> LDSM conflict-free, cp.async clean.
// Loads/kt per warp: 32 LDSM.x4 for 128 mma (0.25 loads/mma).
// mode 0: fp32 out; 2: fp16 x0.125 dim-interleaved (Q);
// 3: fp16 dim-interleaved (K); 4: fp16 V^T token-interleaved.
// ===========================================================================
#define KDIM 1024
#define MT   256
#define NT   128
#define BKH  64
#define ROWB 128                              // bytes per smem row (64 halves)
#define STAGEB ((MT+NT)*ROWB)                 // 49152 B
#define G_SMEM (3*STAGEB)                     // 147456 B

__device__ __forceinline__ void gemm_core(const __half* __restrict__ A,
                                          const __half* __restrict__ W,
                                          float* __restrict__ Cf,
                                          __half* __restrict__ Ch,
                                          int mode, __half* sg) {
    const uint32_t sbase = su32(sg);
    const int tid  = threadIdx.x;
    const int wid  = tid >> 5, lane = tid & 31;
    const int g    = lane >> 2, q = lane & 3;
    const int wr   = wid & 3;          // 4 m-groups x 64 rows
    const int wc   = wid >> 2;         // 2 n-groups x 64 cols
    const int bm   = blockIdx.y * MT;
    const int bn   = blockIdx.x * NT;

    const __half* gA = A + (size_t)bm * KDIM;
    const __half* gW = W + (size_t)bn * KDIM;

    auto cp_stage = [&](int s, int kt) {
        const uint32_t base = sbase + s * STAGEB;
        const int k0 = kt * BKH;
        #pragma unroll
        for (int i = 0; i < 12; i++) {
            int c = tid + i * 256;               // 0..3071
            int row = c >> 3, ch = c & 7;
            uint32_t phys = base + row * ROWB + ((ch ^ (row & 7)) << 4);
            const __half* src = (row < MT)
                ? gA + (size_t)row * KDIM + k0 + ch * 8
                : gW + (size_t)(row - MT) * KDIM + k0 + ch * 8;
            cp16(phys, src);
        }
        cp_commit();
    };

    float acc[4][8][4];
    #pragma unroll
    for (int mi = 0; mi < 4; mi++)
        #pragma unroll
        for (int ni = 0; ni < 8; ni++)
            #pragma unroll
            for (int e = 0; e < 4; e++) acc[mi][ni][e] = 0.f;

    // ldmatrix per-lane address components
    const int swz  = lane & 7;
    const int arow = wr * 64 + (lane & 7) + 8 * ((lane >> 3) & 1);
    const int asel = lane >> 4;                  // k-chunk half (0/1)
    const int brow = wc * 64 + (lane & 7) + 8 * (lane >> 4);
    const int bsel = (lane >> 3) & 1;

    cp_stage(0, 0); cp_stage(1, 1);

    const int NKT = KDIM / BKH;   // 16
    int buf = 0;
    for (int kt = 0; kt < NKT; kt++) {
        cp_wait<1>();
        __syncthreads();
        if (kt + 2 < NKT) {
            int nb = buf + 2; if (nb >= 3) nb -= 3;
            cp_stage(nb, kt + 2);
        } else cp_commit();

        const uint32_t As = sbase + buf * STAGEB;
        const uint32_t Ws = As + MT * ROWB;
        const uint32_t aB = As + arow * ROWB;
        const uint32_t bB = Ws + brow * ROWB;

        #pragma unroll
        for (int kc = 0; kc < 4; kc++) {
            const uint32_t aoff = (uint32_t)(((2*kc + asel) ^ swz) << 4);
            const uint32_t boff = (uint32_t)(((2*kc + bsel) ^ swz) << 4);
            uint32_t av[4][4];
            #pragma unroll
            for (int mi = 0; mi < 4; mi++)
                ldsm4(av[mi][0], av[mi][1], av[mi][2], av[mi][3],
                      aB + mi * (16 * ROWB) + aoff);
            #pragma unroll
            for (int np = 0; np < 4; np++) {
                uint32_t b0, b1, b2, b3;
                ldsm4(b0, b1, b2, b3, bB + np * (16 * ROWB) + boff);
                #pragma unroll
                for (int mi = 0; mi < 4; mi++) {
                    mma16(acc[mi][2*np],   av[mi][0], av[mi][1], av[mi][2], av[mi][3], b0, b1);
                    mma16(acc[mi][2*np+1], av[mi][0], av[mi][1], av[mi][2], av[mi][3], b2, b3);
                }
            }
        }
        buf++; if (buf == 3) buf = 0;
    }

    if (mode == 0) {
        #pragma unroll
        for (int mi = 0; mi < 4; mi++) {
            const int r0 = bm + wr * 64 + mi * 16 + g;
            #pragma unroll
            for (int ni = 0; ni < 8; ni++) {
                const int colb = bn + wc * 64 + ni * 8;
                *(float2*)(Cf + (size_t)r0 * E + colb + 2*q) =
                    make_float2(acc[mi][ni][0], acc[mi][ni][1]);
                *(float2*)(Cf + (size_t)(r0+8) * E + colb + 2*q) =
                    make_float2(acc[mi][ni][2], acc[mi][ni][3]);
            }
        }
    } else if (mode == 4) {
        const int slot0 = 4 * (g >> 1) + (g & 1);
        const int slot1 = slot0 + 2;
        #pragma unroll
        for (int mi = 0; mi < 4; mi++) {
            const int tk0 = bm + wr * 64 + mi * 16 + g;
            const int bi  = tk0 >> 11;
            const int tl  = (tk0 & 2047) & ~15;
            #pragma unroll
            for (int ni = 0; ni < 8; ni++) {
                const int c0 = bn + wc * 64 + ni * 8 + 2 * q;
                const int hh = c0 >> 6, d0 = c0 & 63;
                __half* bp = Ch + ((size_t)(bi * H + hh) * D) * T;
                bp[(size_t)d0 * T + tl + slot0]       = __float2half(acc[mi][ni][0]);
                bp[(size_t)(d0 + 1) * T + tl + slot0] = __float2half(acc[mi][ni][1]);
                bp[(size_t)d0 * T + tl + slot1]       = __float2half(acc[mi][ni][2]);
                bp[(size_t)(d0 + 1) * T + tl + slot1] = __float2half(acc[mi][ni][3]);
            }
        }
    } else {
        const float sc = (mode == 2) ? 0.125f : 1.0f;
        #pragma unroll
        for (int mi = 0; mi < 4; mi++) {
            const int r0 = bm + wr * 64 + mi * 16 + g;
            #pragma unroll
            for (int ni = 0; ni < 8; ni++) {
                const int base = bn + wc * 64 + ((ni >> 1) << 4) + 4*q + 2*(ni & 1);
                *(__half2*)(Ch + (size_t)r0 * E + base) =
                    __floats2half2_rn(sc * acc[mi][ni][0], sc * acc[mi][ni][1]);
                *(__half2*)(Ch + (size_t)(r0+8) * E + base) =
                    __floats2half2_rn(sc * acc[mi][ni][2], sc * acc[mi][ni][3]);
            }
        }
    }
}

__global__ __launch_bounds__(256, 1) void gemm_qkv() {
    extern __shared__ __half sg[];
    if (blockIdx.z == 0)      gemm_core(g_haq, g_hwq, nullptr, g_q,  2, sg);
    else if (blockIdx.z == 1) gemm_core(g_hak, g_hwk, nullptr, g_k,  3, sg);
    else                      gemm_core(g_hav, g_hwv, nullptr, g_vT, 4, sg);
}

__global__ __launch_bounds__(256, 1) void gemm_out(float* __restrict__ C) {
    extern __shared__ __half sg[];
    gemm_core(g_attn, g_hwo, C, nullptr, 0, sg);
}

// ===========================================================================
// Causal flash attention, fp16 m16n8k16, fp32 accum (R12 kernel).
// Epilogue now writes g_attn PLAIN row-major (gemm_out uses ldmatrix).
// ===========================================================================
#define AKH (64*80)
#define AKB (AKH*2)
#define A_SMEM (4*AKB)                    // 40960 B

__global__ __launch_bounds__(256, 2) void attn_tc() {
    extern __shared__ __half sh[];
    const uint32_t sbase = su32(sh);

    const int tid = threadIdx.x;
    const int w = tid >> 5, lane = tid & 31;
    const int g = lane >> 2, q = lane & 3;
    const int b = blockIdx.y / H, h = blockIdx.y % H;
    const int qt = gridDim.x - 1 - blockIdx.x;
    const int qbase = qt * 128;
    const int jmax = 2 * qt + 1;

    const __half* Kg  = g_k + (size_t)(b * T) * E + h * D;
    const __half* Vtg = g_vT + (size_t)((b * H + h) * D) * T;

    const __half* Q0 = g_q + (size_t)(b * T + qbase + w * 16 + g) * E + h * D;
    uint32_t qa[4][4];
    #pragma unroll
    for (int kc = 0; kc < 4; kc++) {
        uint2 x0 = *(const uint2*)&Q0[kc * 16 + 4 * q];
        uint2 x1 = *(const uint2*)&Q0[(size_t)8 * E + kc * 16 + 4 * q];
        qa[kc][0] = x0.x; qa[kc][1] = x1.x; qa[kc][2] = x0.y; qa[kc][3] = x1.y;
    }

    auto stage = [&](int j) {
        const int buf = j & 1;
        const int kbase = j * 64;
        const uint32_t kdst = sbase + buf * AKB;
        const uint32_t vdst = sbase + (2 + buf) * AKB;
        #pragma unroll
        for (int t = 0; t < 4; t++) {
            int c = tid + t * 256;
            if (c < 512) {
                int row = c >> 3, ch = c & 7;
                cp16(kdst + row * 160 + ch * 16,
                     Kg + (size_t)(kbase + row) * E + ch * 8);
            } else {
                int cc = c - 512;
                int row = cc >> 3, ch = cc & 7;
                cp16(vdst + row * 160 + ch * 16,
                     Vtg + (size_t)row * T + kbase + ch * 8);
            }
        }
        cp_commit();
    };

    float oacc[8][4];
    #pragma unroll
    for (int nt = 0; nt < 8; nt++)
        #pragma unroll
        for (int e = 0; e < 4; e++) oacc[nt][e] = 0.f;

    float m0 = -INFINITY, m1 = -INFINITY, l0 = 0.f, l1 = 0.f;
    const int r0g = qbase + w * 16 + g, r1g = r0g + 8;
    const int wmaxrow = qbase + w * 16 + 15;

    stage(0);

    for (int j = 0; j <= jmax; j++) {
        __syncthreads();
        if (j < jmax) stage(j + 1);
        else          cp_commit();
        cp_wait<1>();
        __syncthreads();

        const int kbase = j * 64;
        if (kbase > wmaxrow) continue;

        const __half* Ks = sh + (j & 1) * AKH;
        const __half* Vs = sh + (2 + (j & 1)) * AKH;

        float sacc[8][4];
        #pragma unroll
        for (int nt = 0; nt < 8; nt++) {
            #pragma unroll
            for (int e = 0; e < 4; e++) sacc[nt][e] = 0.f;
            const __half* kp = Ks + (nt * 8 + g) * 80 + 4 * q;
            #pragma unroll
            for (int kc = 0; kc < 4; kc++) {
                uint2 kb = *(const uint2*)&kp[kc * 16];
                mma16(sacc[nt], qa[kc][0], qa[kc][1], qa[kc][2], qa[kc][3],
                      kb.x, kb.y);
            }
        }

        if (kbase + 63 > r0g) {
            #pragma unroll
            for (int nt = 0; nt < 8; nt++) {
                #pragma unroll
                for (int e = 0; e < 2; e++) {
                    int colg = kbase + nt * 8 + 2 * q + e;
                    if (colg > r0g) sacc[nt][e]     = -INFINITY;
                    if (colg > r1g) sacc[nt][2 + e] = -INFINITY;
                }
            }
        }

        float mx0 = -INFINITY, mx1 = -INFINITY;
        #pragma unroll
        for (int nt = 0; nt < 8; nt++) {
            mx0 = fmaxf(mx0, fmaxf(sacc[nt][0], sacc[nt][1]));
            mx1 = fmaxf(mx1, fmaxf(sacc[nt][2], sacc[nt][3]));
        }
        mx0 = fmaxf(mx0, __shfl_xor_sync(0xffffffffu, mx0, 1));
        mx0 = fmaxf(mx0, __shfl_xor_sync(0xffffffffu, mx0, 2));
        mx1 = fmaxf(mx1, __shfl_xor_sync(0xffffffffu, mx1, 1));
        mx1 = fmaxf(mx1, __shfl_xor_sync(0xffffffffu, mx1, 2));
        float mn0 = fmaxf(m0, mx0), mn1 = fmaxf(m1, mx1);
        float sc0 = __expf(m0 - mn0), sc1 = __expf(m1 - mn1);

        float s0 = 0.f, s1 = 0.f;
        uint32_t ph[8][2];
        #pragma unroll
        for (int nt = 0; nt < 8; nt++) {
            float p0 = __expf(sacc[nt][0] - mn0);
            float p1 = __expf(sacc[nt][1] - mn0);
            float p2 = __expf(sacc[nt][2] - mn1);
            float p3 = __expf(sacc[nt][3] - mn1);
            s0 += p0 + p1; s1 += p2 + p3;
            ph[nt][0] = h2u(__floats2half2_rn(p0, p1));
            ph[nt][1] = h2u(__floats2half2_rn(p2, p3));
        }
        s0 += __shfl_xor_sync(0xffffffffu, s0, 1);
        s0 += __shfl_xor_sync(0xffffffffu, s0, 2);
        s1 += __shfl_xor_sync(0xffffffffu, s1, 1);
        s1 += __shfl_xor_sync(0xffffffffu, s1, 2);
        l0 = l0 * sc0 + s0; l1 = l1 * sc1 + s1;
        m0 = mn0; m1 = mn1;
        #pragma unroll
        for (int nt = 0; nt < 8; nt++) {
            oacc[nt][0] *= sc0; oacc[nt][1] *= sc0;
            oacc[nt][2] *= sc1; oacc[nt][3] *= sc1;
        }

        #pragma unroll
        for (int nt = 0; nt < 8; nt++) {
            const __half* vp = Vs + (nt * 8 + g) * 80 + 4 * q;
            #pragma unroll
            for (int kc = 0; kc < 4; kc++) {
                uint2 vb = *(const uint2*)&vp[kc * 16];
                mma16(oacc[nt], ph[2*kc][0], ph[2*kc][1],
                      ph[2*kc+1][0], ph[2*kc+1][1], vb.x, vb.y);
            }
        }
    }

    // Epilogue: PLAIN row-major fp16 (gemm_out consumes via ldmatrix)
    const float inv0 = 1.f / l0, inv1 = 1.f / l1;
    __half* O0 = g_attn + ((size_t)(b * T + r0g)) * E + h * D;
    __half* O1 = g_attn + ((size_t)(b * T + r1g)) * E + h * D;
    #pragma unroll
    for (int nt = 0; nt < 8; nt++) {
        *(__half2*)(O0 + nt * 8 + 2 * q) =
            __floats2half2_rn(oacc[nt][0] * inv0, oacc[nt][1] * inv0);
        *(__half2*)(O1 + nt * 8 + 2 * q) =
            __floats2half2_rn(oacc[nt][2] * inv1, oacc[nt][3] * inv1);
    }
}

// ===========================================================================
// Inputs: queries, keys, values, mask(unused), Wq, Wk, Wv, Wo
// ===========================================================================
extern "C" void kernel_launch(void* const* d_in, const int* in_sizes, int n_in,
                              void* d_out, int out_size) {
    const float* queries = (const float*)d_in[0];
    const float* keys    = (const float*)d_in[1];
    const float* values  = (const float*)d_in[2];
    const float* Wq      = (const float*)d_in[4];
    const float* Wk      = (const float*)d_in[5];
    const float* Wv      = (const float*)d_in[6];
    const float* Wo      = (const float*)d_in[7];

    __half *haq, *hak, *hav, *hwq, *hwk, *hwv, *hwo;
    cudaGetSymbolAddress((void**)&haq, g_haq);
    cudaGetSymbolAddress((void**)&hak, g_hak);
    cudaGetSymbolAddress((void**)&hav, g_hav);
    cudaGetSymbolAddress((void**)&hwq, g_hwq);
    cudaGetSymbolAddress((void**)&hwk, g_hwk);
    cudaGetSymbolAddress((void**)&hwv, g_hwv);
    cudaGetSymbolAddress((void**)&hwo, g_hwo);

    static bool attr_set = false;
    if (!attr_set) {
        cudaFuncSetAttribute(gemm_qkv, cudaFuncAttributeMaxDynamicSharedMemorySize, (int)G_SMEM);
        cudaFuncSetAttribute(gemm_out, cudaFuncAttributeMaxDynamicSharedMemorySize, (int)G_SMEM);
        cudaFuncSetAttribute(attn_tc,  cudaFuncAttributeMaxDynamicSharedMemorySize, (int)A_SMEM);
        attr_set = true;
    }

    PPArgs pa;
    const int NG_IN = BSZ * T * E / 8;   // 1048576
    const int NG_W  = E * E / 8;         // 131072
    pa.src[0] = queries; pa.dst[0] = haq; pa.ngrp[0] = NG_IN;
    pa.src[1] = keys;    pa.dst[1] = hak; pa.ngrp[1] = NG_IN;
    pa.src[2] = values;  pa.dst[2] = hav; pa.ngrp[2] = NG_IN;
    pa.src[3] = Wq;      pa.dst[3] = hwq; pa.ngrp[3] = NG_W;
    pa.src[4] = Wk;      pa.dst[4] = hwk; pa.ngrp[4] = NG_W;
    pa.src[5] = Wv;      pa.dst[5] = hwv; pa.ngrp[5] = NG_W;
    pa.src[6] = Wo;      pa.dst[6] = hwo; pa.ngrp[6] = NG_W;
    prepass<<<dim3(NG_IN / 256, 1, 7), 256>>>(pa);

    dim3 gq(E / NT, (BSZ * T) / MT, 3);     // (8, 16, 3) = 384 CTAs
    gemm_qkv<<<gq, 256, G_SMEM>>>();

    attn_tc<<<dim3(T / 128, BSZ * H), 256, A_SMEM>>>();

    dim3 gg(E / NT, (BSZ * T) / MT);        // (8, 16) = 128 CTAs
    gemm_out<<<gg, 256, G_SMEM>>>((float*)d_out);
}